// round 5
// baseline (speedup 1.0000x reference)
#include <cuda_runtime.h>
#include <cuda_bf16.h>
#include <mma.h>
#include <cstdint>
#include <math.h>

using namespace nvcuda;

// Problem constants
#define H_HEADS 16
#define BATCH   2
#define L       1024
#define D       64
#define USAMP   7097
#define USEL    34
#define DMODEL  (H_HEADS * D)   // 1024
#define MROWS   (BATCH * L)     // 2048

// GEMM tiling
#define KC     64
#define TILEB  16384             // 128 rows * 64 cols * 2B
#define STAGEB (4 * TILEB)       // 64 KB
#define SMEM_DYN (2 * STAGEB)    // 128 KB

// PV tiling
#define NCH 16
#define CHK 64

// ---------------- scratch (static device globals; no allocation) ----------------
__device__ float g_S[BATCH][L][L];
__device__ uint8_t g_cnt8[BATCH][L][16];                // per-(b,j): 16 head counts
__device__ float g_M[BATCH][H_HEADS][L];
__device__ int   g_top[BATCH][H_HEADS][USEL];
__device__ float g_meanv[BATCH][D];
__device__ float g_P[BATCH][H_HEADS][USEL][L];
__device__ float g_rs[BATCH][H_HEADS][USEL];
__device__ float g_pacc[BATCH][H_HEADS][USEL][NCH][64];
__device__ __nv_bfloat16 g_Ahi[MROWS * DMODEL];
__device__ __nv_bfloat16 g_Alo[MROWS * DMODEL];
__device__ __nv_bfloat16 g_Whi[DMODEL * DMODEL];
__device__ __nv_bfloat16 g_Wlo[DMODEL * DMODEL];

// ---------------- threefry2x32 (JAX-compatible) ----------------
__device__ __forceinline__ uint32_t rotl32(uint32_t x, int d) {
    return (x << d) | (x >> (32 - d));
}

__device__ __forceinline__ void threefry2x32(uint32_t k0, uint32_t k1,
                                             uint32_t x0, uint32_t x1,
                                             uint32_t& o0, uint32_t& o1) {
    uint32_t ks2 = k0 ^ k1 ^ 0x1BD11BDAu;
    x0 += k0; x1 += k1;
#define TFR(r) { x0 += x1; x1 = rotl32(x1, (r)); x1 ^= x0; }
    TFR(13) TFR(15) TFR(26) TFR(6)   x0 += k1;  x1 += ks2 + 1u;
    TFR(17) TFR(29) TFR(16) TFR(24)  x0 += ks2; x1 += k0 + 2u;
    TFR(13) TFR(15) TFR(26) TFR(6)   x0 += k0;  x1 += k1 + 3u;
    TFR(17) TFR(29) TFR(16) TFR(24)  x0 += k1;  x1 += ks2 + 4u;
    TFR(13) TFR(15) TFR(26) TFR(6)   x0 += ks2; x1 += k0 + 5u;
#undef TFR
    o0 = x0; o1 = x1;
}

// ---------------- cp.async helpers (sm_80+ PTX; no 'a' features) ----------------
__device__ __forceinline__ uint32_t smem_u32(const void* p) {
    uint32_t a;
    asm("{ .reg .u64 t; cvta.to.shared.u64 t, %1; cvt.u32.u64 %0, t; }" : "=r"(a) : "l"(p));
    return a;
}
__device__ __forceinline__ void cpa16(uint32_t dst, const void* src) {
    asm volatile("cp.async.cg.shared.global [%0], [%1], 16;" :: "r"(dst), "l"(src));
}
#define CPA_COMMIT() asm volatile("cp.async.commit_group;" ::: "memory")
#define CPA_WAIT0()  asm volatile("cp.async.wait_group 0;" ::: "memory")

// ================= K1: mega prologue (scores | split_W | idx hist | meanv) =================
// grid layout (256 threads each):
//   [0, 512):      scores  (b = id>>8, i0 = ((id>>4)&15)*64, j0 = (id&15)*64)
//   [512, 1536):   split_W (t = id-512: k0 = (t>>5)*32, n0 = (t&31)*32)
//   [1536, 1568):  idx_counts (t-1536: h = t&15, b = t>>4)
//   [1568, 1570):  meanv   (b = t-1568)
__global__ void __launch_bounds__(256) k_mega(const float* __restrict__ q,
                                              const float* __restrict__ k,
                                              const float* __restrict__ v,
                                              const float* __restrict__ W) {
    __shared__ union {
        struct { float qs[64][65]; float ks[64][65]; } sc;
        uint32_t hist[L];
        float wt[32][33];
        float part[256];
    } sm;
    int bid = blockIdx.x;
    int tid = threadIdx.x;

    if (bid < 512) {
        // ---- scores: S[b] = q[b] @ k[b]^T ----
        int b  = bid >> 8;
        int i0 = ((bid >> 4) & 15) * 64, j0 = (bid & 15) * 64;
        for (int t = tid; t < 4096; t += 256) {
            int r = t >> 6, c = t & 63;
            sm.sc.qs[r][c] = q[((size_t)b * L + i0 + r) * D + c];
            sm.sc.ks[r][c] = k[((size_t)b * L + j0 + r) * D + c];
        }
        __syncthreads();
        int tx = tid & 15, ty = tid >> 4;
        float acc[4][4] = {};
#pragma unroll 8
        for (int d = 0; d < 64; d++) {
            float a[4], bb[4];
#pragma unroll
            for (int r = 0; r < 4; r++) a[r] = sm.sc.qs[ty * 4 + r][d];
#pragma unroll
            for (int c = 0; c < 4; c++) bb[c] = sm.sc.ks[tx * 4 + c][d];
#pragma unroll
            for (int r = 0; r < 4; r++)
#pragma unroll
                for (int c = 0; c < 4; c++)
                    acc[r][c] += a[r] * bb[c];
        }
#pragma unroll
        for (int r = 0; r < 4; r++)
#pragma unroll
            for (int c = 0; c < 4; c++)
                g_S[b][i0 + ty * 4 + r][j0 + tx * 4 + c] = acc[r][c];
    } else if (bid < 1536) {
        // ---- split + transpose W -> bf16 hi/lo [n][k] ----
        int t = bid - 512;
        int k0 = (t >> 5) * 32, n0 = (t & 31) * 32;
        int tx = tid & 31, ty = tid >> 5;   // 32 x 8
        for (int r = ty; r < 32; r += 8)
            sm.wt[r][tx] = W[(size_t)(k0 + r) * DMODEL + n0 + tx];
        __syncthreads();
        for (int r = ty; r < 32; r += 8) {
            float x = sm.wt[tx][r];
            __nv_bfloat16 hi = __float2bfloat16(x);
            size_t o = (size_t)(n0 + r) * DMODEL + k0 + tx;
            g_Whi[o] = hi;
            g_Wlo[o] = __float2bfloat16(x - __bfloat162float(hi));
        }
    } else if (bid < 1568) {
        // ---- sampled-index histogram for one (h, b), smem counters ----
        int t = bid - 1536;
        int h = t & 15, b = t >> 4;
        for (int j = tid; j < L; j += 256) sm.hist[j] = 0;
        __syncthreads();
        uint32_t hk0, hk1, s0, s1;
        threefry2x32(0u, 42u, 0u, (uint32_t)h, hk0, hk1);
        threefry2x32(hk0, hk1, 0u, 1u, s0, s1);
        for (int i = tid; i < USAMP; i += 256) {
            uint32_t b1, b2;
            threefry2x32(s0, s1, 0u, (uint32_t)(b * USAMP + i), b1, b2);
            atomicAdd(&sm.hist[(b1 ^ b2) & 1023u], 1u);
        }
        __syncthreads();
        for (int j = tid; j < L; j += 256)
            g_cnt8[b][j][h] = (uint8_t)sm.hist[j];
    } else {
        // ---- meanv ----
        int b = bid - 1568;
        int d = tid & 63, g = tid >> 6;
        float s = 0.f;
        for (int kk = g; kk < L; kk += 4)
            s += v[((size_t)b * L + kk) * D + d];
        sm.part[tid] = s;
        __syncthreads();
        if (tid < 64)
            g_meanv[b][tid] = (sm.part[tid] + sm.part[tid + 64] + sm.part[tid + 128] + sm.part[tid + 192]) * (1.0f / 1024.0f);
    }
}

// ================= K2: fused measure (all heads in one S pass) + fill =================
// grid: [0,256) measure blocks (8 rows each); [256, 256+1024) fill blocks
__global__ void __launch_bounds__(256) k_measure_fill() {
    int bid = blockIdx.x;
    int tid = threadIdx.x;
    if (bid < 256) {
        int wid = tid >> 5, lane = tid & 31;
        int rowg = bid * 8 + wid;
        int b = rowg >> 10, row = rowg & 1023;
        const float* Srow = g_S[b][row];
        float mx[16], sv[16];
#pragma unroll
        for (int h = 0; h < 16; h++) { mx[h] = -3.4e38f; sv[h] = 0.f; }
        for (int j = lane; j < L; j += 32) {
            float s = Srow[j];
            uint4 c16 = *(const uint4*)&g_cnt8[b][j][0];
#define HP(wrd, base) { \
            int c0 = (wrd) & 255, c1 = ((wrd) >> 8) & 255, c2 = ((wrd) >> 16) & 255, c3 = (int)((wrd) >> 24); \
            if (c0) mx[(base)]     = fmaxf(mx[(base)],     s);  sv[(base)]     += (float)c0 * s; \
            if (c1) mx[(base) + 1] = fmaxf(mx[(base) + 1], s);  sv[(base) + 1] += (float)c1 * s; \
            if (c2) mx[(base) + 2] = fmaxf(mx[(base) + 2], s);  sv[(base) + 2] += (float)c2 * s; \
            if (c3) mx[(base) + 3] = fmaxf(mx[(base) + 3], s);  sv[(base) + 3] += (float)c3 * s; }
            HP(c16.x, 0) HP(c16.y, 4) HP(c16.z, 8) HP(c16.w, 12)
#undef HP
        }
#pragma unroll
        for (int h = 0; h < 16; h++) {
            float m = mx[h], s = sv[h];
#pragma unroll
            for (int off = 16; off; off >>= 1) {
                m = fmaxf(m, __shfl_down_sync(0xffffffffu, m, off));
                s += __shfl_down_sync(0xffffffffu, s, off);
            }
            if (lane == 0) g_M[b][h][row] = m - s / 7097.0f;
        }
    } else {
        // fill A (bf16 hi/lo) with broadcast mean(v): 1024 blocks x 256 thr x 8 elems
        int t = bid - 256;
        int base = (t * 256 + tid) * 8;       // flat index into [MROWS*DMODEL]
        int b = base >> 20;
#pragma unroll
        for (int e = 0; e < 8; e++) {
            int idx = base + e;
            float x = g_meanv[b][(idx & 63)];
            __nv_bfloat16 hi = __float2bfloat16(x);
            g_Ahi[idx] = hi;
            g_Alo[idx] = __float2bfloat16(x - __bfloat162float(hi));
        }
    }
}

// ================= K3: top-34 + softmax per (b,h), 1024 threads =================
__global__ void __launch_bounds__(1024) k_topk_sm() {
    int h = blockIdx.x, b = blockIdx.y;
    int tid = threadIdx.x;
    int wid = tid >> 5, lane = tid & 31;
    __shared__ unsigned long long sk[32];
    __shared__ int tops[USEL];
    __shared__ float red[32];
    __shared__ float bc;

    float val = g_M[b][h][tid];
    uint32_t ub = __float_as_uint(val);
    uint32_t u = (ub & 0x80000000u) ? ~ub : (ub | 0x80000000u);
    unsigned long long key = ((unsigned long long)u << 10) | (unsigned long long)(1023 - tid);

    for (int t = 0; t < USEL; t++) {
        unsigned long long k2 = key;
#pragma unroll
        for (int off = 16; off; off >>= 1) {
            unsigned long long o = __shfl_down_sync(0xffffffffu, k2, off);
            if (o > k2) k2 = o;
        }
        if (lane == 0) sk[wid] = k2;
        __syncthreads();
        if (wid == 0) {
            unsigned long long k3 = sk[lane];
#pragma unroll
            for (int off = 16; off; off >>= 1) {
                unsigned long long o = __shfl_down_sync(0xffffffffu, k3, off);
                if (o > k3) k3 = o;
            }
            if (lane == 0) {
                sk[0] = k3;
                int widx = 1023 - (int)(k3 & 1023ull);
                tops[t] = widx;
                g_top[b][h][t] = widx;
            }
        }
        __syncthreads();
        int widx = 1023 - (int)(sk[0] & 1023ull);
        if (tid == widx) key = 0ull;
        __syncthreads();
    }

    // softmax rows for the selected queries
    for (int t = 0; t < USEL; t++) {
        int qs = tops[t];
        float s = g_S[b][qs][tid] * 0.03125f;
        float m = s;
#pragma unroll
        for (int off = 16; off; off >>= 1) m = fmaxf(m, __shfl_xor_sync(0xffffffffu, m, off));
        if (lane == 0) red[wid] = m;
        __syncthreads();
        if (wid == 0) {
            float mm = red[lane];
#pragma unroll
            for (int off = 16; off; off >>= 1) mm = fmaxf(mm, __shfl_xor_sync(0xffffffffu, mm, off));
            if (lane == 0) bc = mm;
        }
        __syncthreads();
        float e = __expf(s - bc);
        g_P[b][h][t][tid] = e;
        float su = e;
#pragma unroll
        for (int off = 16; off; off >>= 1) su += __shfl_xor_sync(0xffffffffu, su, off);
        if (lane == 0) red[wid] = su;
        __syncthreads();
        if (wid == 0) {
            float ss = red[lane];
#pragma unroll
            for (int off = 16; off; off >>= 1) ss += __shfl_xor_sync(0xffffffffu, ss, off);
            if (lane == 0) g_rs[b][h][t] = 1.0f / ss;
        }
        __syncthreads();
    }
}

// ================= K4: PV partials (v slice cached in smem) =================
__global__ void k_pv(const float* __restrict__ v) {
    __shared__ float vs[CHK][64];
    __shared__ float ps[USEL][CHK];
    int ch = blockIdx.x, h = blockIdx.y, b = blockIdx.z;
    int k0 = ch * CHK;
    int tid = threadIdx.x;

    for (int u = tid; u < CHK * 64 / 4; u += 256) {
        int kk = u >> 4, c4 = (u & 15) * 4;
        *(float4*)&vs[kk][c4] = *(const float4*)&v[((size_t)b * L + k0 + kk) * D + c4];
    }
    for (int u = tid; u < USEL * CHK / 4; u += 256) {
        int row = u / (CHK / 4), c4 = (u % (CHK / 4)) * 4;
        *(float4*)&ps[row][c4] = *(const float4*)&g_P[b][h][row][k0 + c4];
    }
    __syncthreads();

    int r = tid >> 6, d = tid & 63;
    float acc[9];
#pragma unroll
    for (int i = 0; i < 9; i++) acc[i] = 0.f;

    for (int kk = 0; kk < CHK; kk += 4) {
        float v0 = vs[kk][d], v1 = vs[kk + 1][d], v2 = vs[kk + 2][d], v3 = vs[kk + 3][d];
#pragma unroll
        for (int i = 0; i < 9; i++) {
            int row = r + i * 4;
            if (row < USEL) {
                float4 p4 = *(float4*)&ps[row][kk];
                acc[i] += p4.x * v0 + p4.y * v1 + p4.z * v2 + p4.w * v3;
            }
        }
    }
#pragma unroll
    for (int i = 0; i < 9; i++) {
        int row = r + i * 4;
        if (row < USEL)
            g_pacc[b][h][row][ch][d] = acc[i];
    }
}

// ================= K5: sum partials, normalize, write bf16 split rows =================
__global__ void k_write() {
    int bh = blockIdx.x;
    int b = bh >> 4, h = bh & 15;
    int tid = threadIdx.x;
    int r = tid >> 6, d = tid & 63;
    for (int row = r; row < USEL; row += 4) {
        float s = 0.f;
#pragma unroll
        for (int c = 0; c < NCH; c++) s += g_pacc[b][h][row][c][d];
        float val = s * g_rs[b][h][row];
        int qs = g_top[b][h][row];
        size_t idx = (size_t)(b * L + qs) * DMODEL + h * D + d;
        __nv_bfloat16 hi = __float2bfloat16(val);
        g_Ahi[idx] = hi;
        g_Alo[idx] = __float2bfloat16(val - __bfloat162float(hi));
    }
}

// ================= K6: wmma GEMM with cp.async double buffering =================
__device__ __forceinline__ void issue_stage(uint32_t sbase, int bm, int bn, int k0, int tid) {
#pragma unroll
    for (int u0 = 0; u0 < 1024; u0 += 256) {
        int u = u0 + tid;
        int row = u >> 3, c8 = (u & 7) * 8;
        size_t ga = (size_t)(bm + row) * DMODEL + k0 + c8;
        size_t gb = (size_t)(bn + row) * DMODEL + k0 + c8;
        uint32_t so = (uint32_t)u * 16;
        cpa16(sbase + so,              &g_Ahi[ga]);
        cpa16(sbase + TILEB + so,      &g_Alo[ga]);
        cpa16(sbase + 2 * TILEB + so,  &g_Whi[gb]);
        cpa16(sbase + 3 * TILEB + so,  &g_Wlo[gb]);
    }
}

__global__ void __launch_bounds__(256, 1) k_proj_wmma(const float* __restrict__ bias,
                                                      float* __restrict__ out) {
    extern __shared__ __nv_bfloat16 smd[];
    uint32_t sbase = smem_u32(smd);
    int tid = threadIdx.x;
    int w = tid >> 5;
    int wm = w & 1;
    int wn = w >> 1;
    int bm = blockIdx.y * 128, bn = blockIdx.x * 128;

    wmma::fragment<wmma::accumulator, 16, 16, 16, float> acc[4][2];
#pragma unroll
    for (int i = 0; i < 4; i++)
#pragma unroll
        for (int j = 0; j < 2; j++)
            wmma::fill_fragment(acc[i][j], 0.0f);

    issue_stage(sbase, bm, bn, 0, tid);
    CPA_COMMIT();

    const int NCHUNK = DMODEL / KC;   // 16
    for (int c = 0; c < NCHUNK; c++) {
        CPA_WAIT0();
        __syncthreads();
        if (c + 1 < NCHUNK) {
            issue_stage(sbase + ((c + 1) & 1) * STAGEB, bm, bn, (c + 1) * KC, tid);
            CPA_COMMIT();
        }
        const __nv_bfloat16* s = smd + (c & 1) * (STAGEB / 2);   // elements, not bytes
        const __nv_bfloat16* Ahi = s;
        const __nv_bfloat16* Alo = s + TILEB / 2;
        const __nv_bfloat16* Bhi = s + TILEB;
        const __nv_bfloat16* Blo = s + 3 * TILEB / 2;
#pragma unroll
        for (int kk = 0; kk < KC; kk += 16) {
            wmma::fragment<wmma::matrix_a, 16, 16, 16, __nv_bfloat16, wmma::row_major> ah[4], al[4];
            wmma::fragment<wmma::matrix_b, 16, 16, 16, __nv_bfloat16, wmma::col_major> bh[2], bl[2];
#pragma unroll
            for (int i = 0; i < 4; i++) {
                wmma::load_matrix_sync(ah[i], Ahi + (wm * 64 + i * 16) * KC + kk, KC);
                wmma::load_matrix_sync(al[i], Alo + (wm * 64 + i * 16) * KC + kk, KC);
            }
#pragma unroll
            for (int j = 0; j < 2; j++) {
                wmma::load_matrix_sync(bh[j], Bhi + (wn * 32 + j * 16) * KC + kk, KC);
                wmma::load_matrix_sync(bl[j], Blo + (wn * 32 + j * 16) * KC + kk, KC);
            }
#pragma unroll
            for (int i = 0; i < 4; i++)
#pragma unroll
                for (int j = 0; j < 2; j++) {
                    wmma::mma_sync(acc[i][j], ah[i], bh[j], acc[i][j]);
                    wmma::mma_sync(acc[i][j], ah[i], bl[j], acc[i][j]);
                    wmma::mma_sync(acc[i][j], al[i], bh[j], acc[i][j]);
                }
        }
        __syncthreads();
    }

    float* fs = (float*)smd;
#pragma unroll
    for (int i = 0; i < 4; i++)
#pragma unroll
        for (int j = 0; j < 2; j++)
            wmma::store_matrix_sync(&fs[(wm * 64 + i * 16) * 128 + wn * 32 + j * 16],
                                    acc[i][j], 128, wmma::mem_row_major);
    __syncthreads();
    for (int u = tid; u < 128 * 128 / 4; u += 256) {
        int row = u >> 5, c4 = (u & 31) * 4;
        float4 vv = *(float4*)&fs[row * 128 + c4];
        float4 bb = *(const float4*)&bias[bn + c4];
        vv.x += bb.x; vv.y += bb.y; vv.z += bb.z; vv.w += bb.w;
        *(float4*)&out[(size_t)(bm + row) * DMODEL + bn + c4] = vv;
    }
}

// ---------------- launch ----------------
extern "C" void kernel_launch(void* const* d_in, const int* in_sizes, int n_in,
                              void* d_out, int out_size) {
    const float* q    = (const float*)d_in[0];
    const float* k    = (const float*)d_in[1];
    const float* v    = (const float*)d_in[2];
    const float* W    = (const float*)d_in[3];
    const float* bias = (const float*)d_in[4];
    float* out = (float*)d_out;

    cudaFuncSetAttribute(k_proj_wmma, cudaFuncAttributeMaxDynamicSharedMemorySize, SMEM_DYN);

    k_mega<<<1570, 256>>>(q, k, v, W);

    k_measure_fill<<<256 + 1024, 256>>>();

    dim3 gT(H_HEADS, BATCH);
    k_topk_sm<<<gT, 1024>>>();

    dim3 gPV(NCH, H_HEADS, BATCH);
    k_pv<<<gPV, 256>>>(v);

    k_write<<<BATCH * H_HEADS, 256>>>();

    dim3 gG(DMODEL / 128, MROWS / 128);
    k_proj_wmma<<<gG, 256, SMEM_DYN>>>(bias, out);
}

// round 6
// speedup vs baseline: 1.2473x; 1.2473x over previous
#include <cuda_runtime.h>
#include <cuda_bf16.h>
#include <mma.h>
#include <cstdint>
#include <math.h>

using namespace nvcuda;

// Problem constants
#define H_HEADS 16
#define BATCH   2
#define L       1024
#define D       64
#define USAMP   7097
#define USEL    34
#define DMODEL  (H_HEADS * D)   // 1024
#define MROWS   (BATCH * L)     // 2048

// GEMM tiling (round-4 proven config)
#define KC    32
#define TILE  (128 * KC)
#define SMEM_DYN 65536

// PV tiling
#define NCH 16
#define CHK 64

// ---------------- scratch (static device globals; no allocation) ----------------
__device__ float g_S[BATCH][L][L];
__device__ uint8_t g_cnt8[BATCH][L][16];                // per-(b,j): 16 head counts
__device__ float g_M[BATCH][H_HEADS][L];
__device__ int   g_top[BATCH][H_HEADS][USEL];
__device__ float g_meanv[BATCH][D];
__device__ float g_P[BATCH][H_HEADS][USEL][L];
__device__ float g_rs[BATCH][H_HEADS][USEL];
__device__ float g_pacc[BATCH][H_HEADS][USEL][NCH][64];
__device__ __nv_bfloat16 g_Ahi[MROWS * DMODEL];
__device__ __nv_bfloat16 g_Alo[MROWS * DMODEL];
__device__ __nv_bfloat16 g_Whi[DMODEL * DMODEL];
__device__ __nv_bfloat16 g_Wlo[DMODEL * DMODEL];

// ---------------- threefry2x32 (JAX-compatible) ----------------
__device__ __forceinline__ uint32_t rotl32(uint32_t x, int d) {
    return (x << d) | (x >> (32 - d));
}

__device__ __forceinline__ void threefry2x32(uint32_t k0, uint32_t k1,
                                             uint32_t x0, uint32_t x1,
                                             uint32_t& o0, uint32_t& o1) {
    uint32_t ks2 = k0 ^ k1 ^ 0x1BD11BDAu;
    x0 += k0; x1 += k1;
#define TFR(r) { x0 += x1; x1 = rotl32(x1, (r)); x1 ^= x0; }
    TFR(13) TFR(15) TFR(26) TFR(6)   x0 += k1;  x1 += ks2 + 1u;
    TFR(17) TFR(29) TFR(16) TFR(24)  x0 += ks2; x1 += k0 + 2u;
    TFR(13) TFR(15) TFR(26) TFR(6)   x0 += k0;  x1 += k1 + 3u;
    TFR(17) TFR(29) TFR(16) TFR(24)  x0 += k1;  x1 += ks2 + 4u;
    TFR(13) TFR(15) TFR(26) TFR(6)   x0 += ks2; x1 += k0 + 5u;
#undef TFR
    o0 = x0; o1 = x1;
}

// ================= K1: mega prologue (scores | split_W | idx hist | meanv) =================
__global__ void __launch_bounds__(256) k_mega(const float* __restrict__ q,
                                              const float* __restrict__ k,
                                              const float* __restrict__ v,
                                              const float* __restrict__ W) {
    __shared__ union {
        struct { float qs[64][65]; float ks[64][65]; } sc;
        uint32_t hist[L];
        float wt[32][33];
        float part[256];
    } sm;
    int bid = blockIdx.x;
    int tid = threadIdx.x;

    if (bid < 512) {
        // ---- scores: S[b] = q[b] @ k[b]^T ----
        int b  = bid >> 8;
        int i0 = ((bid >> 4) & 15) * 64, j0 = (bid & 15) * 64;
        for (int t = tid; t < 4096; t += 256) {
            int r = t >> 6, c = t & 63;
            sm.sc.qs[r][c] = q[((size_t)b * L + i0 + r) * D + c];
            sm.sc.ks[r][c] = k[((size_t)b * L + j0 + r) * D + c];
        }
        __syncthreads();
        int tx = tid & 15, ty = tid >> 4;
        float acc[4][4] = {};
#pragma unroll 8
        for (int d = 0; d < 64; d++) {
            float a[4], bb[4];
#pragma unroll
            for (int r = 0; r < 4; r++) a[r] = sm.sc.qs[ty * 4 + r][d];
#pragma unroll
            for (int c = 0; c < 4; c++) bb[c] = sm.sc.ks[tx * 4 + c][d];
#pragma unroll
            for (int r = 0; r < 4; r++)
#pragma unroll
                for (int c = 0; c < 4; c++)
                    acc[r][c] += a[r] * bb[c];
        }
#pragma unroll
        for (int r = 0; r < 4; r++)
#pragma unroll
            for (int c = 0; c < 4; c++)
                g_S[b][i0 + ty * 4 + r][j0 + tx * 4 + c] = acc[r][c];
    } else if (bid < 1536) {
        // ---- split + transpose W -> bf16 hi/lo [n][k] ----
        int t = bid - 512;
        int k0 = (t >> 5) * 32, n0 = (t & 31) * 32;
        int tx = tid & 31, ty = tid >> 5;   // 32 x 8
        for (int r = ty; r < 32; r += 8)
            sm.wt[r][tx] = W[(size_t)(k0 + r) * DMODEL + n0 + tx];
        __syncthreads();
        for (int r = ty; r < 32; r += 8) {
            float x = sm.wt[tx][r];
            __nv_bfloat16 hi = __float2bfloat16(x);
            size_t o = (size_t)(n0 + r) * DMODEL + k0 + tx;
            g_Whi[o] = hi;
            g_Wlo[o] = __float2bfloat16(x - __bfloat162float(hi));
        }
    } else if (bid < 1568) {
        // ---- sampled-index histogram for one (h, b), smem counters ----
        int t = bid - 1536;
        int h = t & 15, b = t >> 4;
        for (int j = tid; j < L; j += 256) sm.hist[j] = 0;
        __syncthreads();
        uint32_t hk0, hk1, s0, s1;
        threefry2x32(0u, 42u, 0u, (uint32_t)h, hk0, hk1);
        threefry2x32(hk0, hk1, 0u, 1u, s0, s1);
        for (int i = tid; i < USAMP; i += 256) {
            uint32_t b1, b2;
            threefry2x32(s0, s1, 0u, (uint32_t)(b * USAMP + i), b1, b2);
            atomicAdd(&sm.hist[(b1 ^ b2) & 1023u], 1u);
        }
        __syncthreads();
        for (int j = tid; j < L; j += 256)
            g_cnt8[b][j][h] = (uint8_t)sm.hist[j];
    } else {
        // ---- meanv ----
        int b = bid - 1568;
        int d = tid & 63, g = tid >> 6;
        float s = 0.f;
        for (int kk = g; kk < L; kk += 4)
            s += v[((size_t)b * L + kk) * D + d];
        sm.part[tid] = s;
        __syncthreads();
        if (tid < 64)
            g_meanv[b][tid] = (sm.part[tid] + sm.part[tid + 64] + sm.part[tid + 128] + sm.part[tid + 192]) * (1.0f / 1024.0f);
    }
}

// ================= K2: fused measure (all 16 heads, one S pass) + fill =================
__global__ void __launch_bounds__(256) k_measure_fill() {
    int bid = blockIdx.x;
    int tid = threadIdx.x;
    if (bid < 256) {
        int wid = tid >> 5, lane = tid & 31;
        int rowg = bid * 8 + wid;
        int b = rowg >> 10, row = rowg & 1023;
        const float* Srow = g_S[b][row];
        float mx[16], sv[16];
#pragma unroll
        for (int h = 0; h < 16; h++) { mx[h] = -3.4e38f; sv[h] = 0.f; }
        for (int j = lane; j < L; j += 32) {
            float s = Srow[j];
            uint4 c16 = *(const uint4*)&g_cnt8[b][j][0];
#define HP(wrd, base) { \
            int c0 = (wrd) & 255, c1 = ((wrd) >> 8) & 255, c2 = ((wrd) >> 16) & 255, c3 = (int)((wrd) >> 24); \
            if (c0) mx[(base)]     = fmaxf(mx[(base)],     s);  sv[(base)]     += (float)c0 * s; \
            if (c1) mx[(base) + 1] = fmaxf(mx[(base) + 1], s);  sv[(base) + 1] += (float)c1 * s; \
            if (c2) mx[(base) + 2] = fmaxf(mx[(base) + 2], s);  sv[(base) + 2] += (float)c2 * s; \
            if (c3) mx[(base) + 3] = fmaxf(mx[(base) + 3], s);  sv[(base) + 3] += (float)c3 * s; }
            HP(c16.x, 0) HP(c16.y, 4) HP(c16.z, 8) HP(c16.w, 12)
#undef HP
        }
#pragma unroll
        for (int h = 0; h < 16; h++) {
            float m = mx[h], s = sv[h];
#pragma unroll
            for (int off = 16; off; off >>= 1) {
                m = fmaxf(m, __shfl_down_sync(0xffffffffu, m, off));
                s += __shfl_down_sync(0xffffffffu, s, off);
            }
            if (lane == 0) g_M[b][h][row] = m - s / 7097.0f;
        }
    } else {
        int t = bid - 256;
        int base = (t * 256 + tid) * 8;
        int b = base >> 20;
#pragma unroll
        for (int e = 0; e < 8; e++) {
            int idx = base + e;
            float x = g_meanv[b][(idx & 63)];
            __nv_bfloat16 hi = __float2bfloat16(x);
            g_Ahi[idx] = hi;
            g_Alo[idx] = __float2bfloat16(x - __bfloat162float(hi));
        }
    }
}

// ================= K3: top-34 via packed-u64 shfl reduce (1024 threads) =================
__global__ void __launch_bounds__(1024) k_topk() {
    int h = blockIdx.x, b = blockIdx.y;
    int tid = threadIdx.x;
    int wid = tid >> 5, lane = tid & 31;
    __shared__ unsigned long long sk[32];

    float val = g_M[b][h][tid];
    uint32_t ub = __float_as_uint(val);
    uint32_t u = (ub & 0x80000000u) ? ~ub : (ub | 0x80000000u);
    unsigned long long key = ((unsigned long long)u << 10) | (unsigned long long)(1023 - tid);

    for (int t = 0; t < USEL; t++) {
        unsigned long long k2 = key;
#pragma unroll
        for (int off = 16; off; off >>= 1) {
            unsigned long long o = __shfl_down_sync(0xffffffffu, k2, off);
            if (o > k2) k2 = o;
        }
        if (lane == 0) sk[wid] = k2;
        __syncthreads();
        if (wid == 0) {
            unsigned long long k3 = sk[lane];
#pragma unroll
            for (int off = 16; off; off >>= 1) {
                unsigned long long o = __shfl_down_sync(0xffffffffu, k3, off);
                if (o > k3) k3 = o;
            }
            if (lane == 0) {
                sk[0] = k3;
                g_top[b][h][t] = 1023 - (int)(k3 & 1023ull);
            }
        }
        __syncthreads();
        int widx = 1023 - (int)(sk[0] & 1023ull);
        if (tid == widx) key = 0ull;
        __syncthreads();
    }
}

// ================= K4: softmax weights for selected rows (1088 blocks) =================
__global__ void k_softmax() {
    int i = blockIdx.x, h = blockIdx.y, b = blockIdx.z;
    int qs = g_top[b][h][i];
    __shared__ float red[256];
    int tid = threadIdx.x;
    const float* Srow = g_S[b][qs];

    float mx = -3.4e38f;
    for (int j = tid; j < L; j += 256) mx = fmaxf(mx, Srow[j]);
    red[tid] = mx;
    __syncthreads();
    for (int s = 128; s; s >>= 1) { if (tid < s) red[tid] = fmaxf(red[tid], red[tid + s]); __syncthreads(); }
    float mxs = red[0] * 0.03125f;
    __syncthreads();

    float sum = 0.f;
    float* Prow = g_P[b][h][i];
    for (int j = tid; j < L; j += 256) {
        float e = __expf(Srow[j] * 0.03125f - mxs);
        Prow[j] = e;
        sum += e;
    }
    red[tid] = sum;
    __syncthreads();
    for (int s = 128; s; s >>= 1) { if (tid < s) red[tid] += red[tid + s]; __syncthreads(); }
    if (tid == 0) g_rs[b][h][i] = 1.0f / red[0];
}

// ================= K5: PV partials (v slice cached in smem) =================
__global__ void k_pv(const float* __restrict__ v) {
    __shared__ float vs[CHK][64];
    __shared__ float ps[USEL][CHK];
    int ch = blockIdx.x, h = blockIdx.y, b = blockIdx.z;
    int k0 = ch * CHK;
    int tid = threadIdx.x;

    for (int u = tid; u < CHK * 64 / 4; u += 256) {
        int kk = u >> 4, c4 = (u & 15) * 4;
        *(float4*)&vs[kk][c4] = *(const float4*)&v[((size_t)b * L + k0 + kk) * D + c4];
    }
    for (int u = tid; u < USEL * CHK / 4; u += 256) {
        int row = u / (CHK / 4), c4 = (u % (CHK / 4)) * 4;
        *(float4*)&ps[row][c4] = *(const float4*)&g_P[b][h][row][k0 + c4];
    }
    __syncthreads();

    int r = tid >> 6, d = tid & 63;
    float acc[9];
#pragma unroll
    for (int i = 0; i < 9; i++) acc[i] = 0.f;

    for (int kk = 0; kk < CHK; kk += 4) {
        float v0 = vs[kk][d], v1 = vs[kk + 1][d], v2 = vs[kk + 2][d], v3 = vs[kk + 3][d];
#pragma unroll
        for (int i = 0; i < 9; i++) {
            int row = r + i * 4;
            if (row < USEL) {
                float4 p4 = *(float4*)&ps[row][kk];
                acc[i] += p4.x * v0 + p4.y * v1 + p4.z * v2 + p4.w * v3;
            }
        }
    }
#pragma unroll
    for (int i = 0; i < 9; i++) {
        int row = r + i * 4;
        if (row < USEL)
            g_pacc[b][h][row][ch][d] = acc[i];
    }
}

// ================= K6: sum partials, normalize, write bf16 split rows =================
__global__ void k_write() {
    int bh = blockIdx.x;
    int b = bh >> 4, h = bh & 15;
    int tid = threadIdx.x;
    int r = tid >> 6, d = tid & 63;
    for (int row = r; row < USEL; row += 4) {
        float s = 0.f;
#pragma unroll
        for (int c = 0; c < NCH; c++) s += g_pacc[b][h][row][c][d];
        float val = s * g_rs[b][h][row];
        int qs = g_top[b][h][row];
        size_t idx = (size_t)(b * L + qs) * DMODEL + h * D + d;
        __nv_bfloat16 hi = __float2bfloat16(val);
        g_Ahi[idx] = hi;
        g_Alo[idx] = __float2bfloat16(val - __bfloat162float(hi));
    }
}

// ================= K7: wmma GEMM (round-4 proven: KC=32, LDG/STS double buffer) =================
__device__ __forceinline__ void load_stage(__nv_bfloat16* s, int bm, int bn, int k0, int tid) {
    for (int u = tid; u < 512; u += 256) {
        int row = u >> 2, c = (u & 3) * 8;
        size_t ga = (size_t)(bm + row) * DMODEL + k0 + c;
        size_t gb = (size_t)(bn + row) * DMODEL + k0 + c;
        int so = row * KC + c;
        *(uint4*)&s[so]            = *(const uint4*)&g_Ahi[ga];
        *(uint4*)&s[TILE + so]     = *(const uint4*)&g_Alo[ga];
        *(uint4*)&s[2 * TILE + so] = *(const uint4*)&g_Whi[gb];
        *(uint4*)&s[3 * TILE + so] = *(const uint4*)&g_Wlo[gb];
    }
}

__global__ void __launch_bounds__(256, 1) k_proj_wmma(const float* __restrict__ bias,
                                                      float* __restrict__ out) {
    extern __shared__ __nv_bfloat16 sm[];
    int tid = threadIdx.x;
    int w = tid >> 5;
    int wm = w & 1;
    int wn = w >> 1;
    int bm = blockIdx.y * 128, bn = blockIdx.x * 128;

    wmma::fragment<wmma::accumulator, 16, 16, 16, float> acc[4][2];
#pragma unroll
    for (int i = 0; i < 4; i++)
#pragma unroll
        for (int j = 0; j < 2; j++)
            wmma::fill_fragment(acc[i][j], 0.0f);

    load_stage(sm, bm, bn, 0, tid);
    __syncthreads();

    for (int c = 0; c < DMODEL / KC; c++) {
        int cur = c & 1;
        if (c + 1 < DMODEL / KC)
            load_stage(sm + (cur ^ 1) * 4 * TILE, bm, bn, (c + 1) * KC, tid);

        const __nv_bfloat16* s   = sm + cur * 4 * TILE;
        const __nv_bfloat16* Ahi = s;
        const __nv_bfloat16* Alo = s + TILE;
        const __nv_bfloat16* Bhi = s + 2 * TILE;
        const __nv_bfloat16* Blo = s + 3 * TILE;
#pragma unroll
        for (int kk = 0; kk < KC; kk += 16) {
            wmma::fragment<wmma::matrix_a, 16, 16, 16, __nv_bfloat16, wmma::row_major> ah[4], al[4];
            wmma::fragment<wmma::matrix_b, 16, 16, 16, __nv_bfloat16, wmma::col_major> bh[2], bl[2];
#pragma unroll
            for (int i = 0; i < 4; i++) {
                wmma::load_matrix_sync(ah[i], Ahi + (wm * 64 + i * 16) * KC + kk, KC);
                wmma::load_matrix_sync(al[i], Alo + (wm * 64 + i * 16) * KC + kk, KC);
            }
#pragma unroll
            for (int j = 0; j < 2; j++) {
                wmma::load_matrix_sync(bh[j], Bhi + (wn * 32 + j * 16) * KC + kk, KC);
                wmma::load_matrix_sync(bl[j], Blo + (wn * 32 + j * 16) * KC + kk, KC);
            }
#pragma unroll
            for (int i = 0; i < 4; i++)
#pragma unroll
                for (int j = 0; j < 2; j++) {
                    wmma::mma_sync(acc[i][j], ah[i], bh[j], acc[i][j]);
                    wmma::mma_sync(acc[i][j], ah[i], bl[j], acc[i][j]);
                    wmma::mma_sync(acc[i][j], al[i], bh[j], acc[i][j]);
                }
        }
        __syncthreads();
    }

    float* fs = (float*)sm;
#pragma unroll
    for (int i = 0; i < 4; i++)
#pragma unroll
        for (int j = 0; j < 2; j++)
            wmma::store_matrix_sync(&fs[(wm * 64 + i * 16) * 128 + wn * 32 + j * 16],
                                    acc[i][j], 128, wmma::mem_row_major);
    __syncthreads();
    for (int u = tid; u < 128 * 128 / 4; u += 256) {
        int row = u >> 5, c4 = (u & 31) * 4;
        float4 vv = *(float4*)&fs[row * 128 + c4];
        float4 bb = *(const float4*)&bias[bn + c4];
        vv.x += bb.x; vv.y += bb.y; vv.z += bb.z; vv.w += bb.w;
        *(float4*)&out[(size_t)(bm + row) * DMODEL + bn + c4] = vv;
    }
}

// ---------------- launch ----------------
extern "C" void kernel_launch(void* const* d_in, const int* in_sizes, int n_in,
                              void* d_out, int out_size) {
    const float* q    = (const float*)d_in[0];
    const float* k    = (const float*)d_in[1];
    const float* v    = (const float*)d_in[2];
    const float* W    = (const float*)d_in[3];
    const float* bias = (const float*)d_in[4];
    float* out = (float*)d_out;

    cudaFuncSetAttribute(k_proj_wmma, cudaFuncAttributeMaxDynamicSharedMemorySize, SMEM_DYN);

    k_mega<<<1570, 256>>>(q, k, v, W);

    k_measure_fill<<<256 + 1024, 256>>>();

    dim3 gT(H_HEADS, BATCH);
    k_topk<<<gT, 1024>>>();

    dim3 gSm(USEL, H_HEADS, BATCH);
    k_softmax<<<gSm, 256>>>();

    dim3 gPV(NCH, H_HEADS, BATCH);
    k_pv<<<gPV, 256>>>(v);

    k_write<<<BATCH * H_HEADS, 256>>>();

    dim3 gG(DMODEL / 128, MROWS / 128);
    k_proj_wmma<<<gG, 256, SMEM_DYN>>>(bias, out);
}

// round 7
// speedup vs baseline: 1.5003x; 1.2029x over previous
#include <cuda_runtime.h>
#include <cuda_bf16.h>
#include <mma.h>
#include <cstdint>
#include <math.h>

using namespace nvcuda;

// Problem constants
#define H_HEADS 16
#define BATCH   2
#define L       1024
#define D       64
#define USAMP   7097
#define USEL    34
#define DMODEL  (H_HEADS * D)   // 1024
#define MROWS   (BATCH * L)     // 2048

// GEMM tiling: KC=32 logical K-chunk, padded smem stride 40 (80B -> conflict-free LDSM)
#define KC    32
#define SPAD  40
#define TILE  (128 * SPAD)
#define SMEM_DYN (2 * 4 * TILE * 2)   // 81920 bytes

// PV tiling
#define NCH 16
#define CHK 64

// ---------------- scratch (static device globals; no allocation) ----------------
__device__ float g_S[BATCH][L][L];
__device__ uint8_t g_cnt8[BATCH][L][16];
__device__ float g_M[BATCH][H_HEADS][L];
__device__ int   g_top[BATCH][H_HEADS][USEL];
__device__ float g_meanv[BATCH][D];
__device__ float g_P[BATCH][H_HEADS][USEL][L];
__device__ float g_rs[BATCH][H_HEADS][USEL];
__device__ float g_pacc[BATCH][H_HEADS][USEL][NCH][64];
__device__ __nv_bfloat16 g_Ahi[MROWS * DMODEL];
__device__ __nv_bfloat16 g_Alo[MROWS * DMODEL];
__device__ __nv_bfloat16 g_Whi[DMODEL * DMODEL];
__device__ __nv_bfloat16 g_Wlo[DMODEL * DMODEL];

// ---------------- threefry2x32 (JAX-compatible) ----------------
__device__ __forceinline__ uint32_t rotl32(uint32_t x, int d) {
    return (x << d) | (x >> (32 - d));
}

__device__ __forceinline__ void threefry2x32(uint32_t k0, uint32_t k1,
                                             uint32_t x0, uint32_t x1,
                                             uint32_t& o0, uint32_t& o1) {
    uint32_t ks2 = k0 ^ k1 ^ 0x1BD11BDAu;
    x0 += k0; x1 += k1;
#define TFR(r) { x0 += x1; x1 = rotl32(x1, (r)); x1 ^= x0; }
    TFR(13) TFR(15) TFR(26) TFR(6)   x0 += k1;  x1 += ks2 + 1u;
    TFR(17) TFR(29) TFR(16) TFR(24)  x0 += ks2; x1 += k0 + 2u;
    TFR(13) TFR(15) TFR(26) TFR(6)   x0 += k0;  x1 += k1 + 3u;
    TFR(17) TFR(29) TFR(16) TFR(24)  x0 += k1;  x1 += ks2 + 4u;
    TFR(13) TFR(15) TFR(26) TFR(6)   x0 += ks2; x1 += k0 + 5u;
#undef TFR
    o0 = x0; o1 = x1;
}

// ================= K1: mega prologue (scores | split_W | idx hist | meanv) =================
__global__ void __launch_bounds__(256) k_mega(const float* __restrict__ q,
                                              const float* __restrict__ k,
                                              const float* __restrict__ v,
                                              const float* __restrict__ W) {
    __shared__ union {
        struct { float qs[64][65]; float ks[64][65]; } sc;
        uint32_t hist[L];
        float wt[32][33];
        float part[256];
    } sm;
    int bid = blockIdx.x;
    int tid = threadIdx.x;

    if (bid < 512) {
        int b  = bid >> 8;
        int i0 = ((bid >> 4) & 15) * 64, j0 = (bid & 15) * 64;
        for (int t = tid; t < 4096; t += 256) {
            int r = t >> 6, c = t & 63;
            sm.sc.qs[r][c] = q[((size_t)b * L + i0 + r) * D + c];
            sm.sc.ks[r][c] = k[((size_t)b * L + j0 + r) * D + c];
        }
        __syncthreads();
        int tx = tid & 15, ty = tid >> 4;
        float acc[4][4] = {};
#pragma unroll 8
        for (int d = 0; d < 64; d++) {
            float a[4], bb[4];
#pragma unroll
            for (int r = 0; r < 4; r++) a[r] = sm.sc.qs[ty * 4 + r][d];
#pragma unroll
            for (int c = 0; c < 4; c++) bb[c] = sm.sc.ks[tx * 4 + c][d];
#pragma unroll
            for (int r = 0; r < 4; r++)
#pragma unroll
                for (int c = 0; c < 4; c++)
                    acc[r][c] += a[r] * bb[c];
        }
#pragma unroll
        for (int r = 0; r < 4; r++)
#pragma unroll
            for (int c = 0; c < 4; c++)
                g_S[b][i0 + ty * 4 + r][j0 + tx * 4 + c] = acc[r][c];
    } else if (bid < 1536) {
        int t = bid - 512;
        int k0 = (t >> 5) * 32, n0 = (t & 31) * 32;
        int tx = tid & 31, ty = tid >> 5;
        for (int r = ty; r < 32; r += 8)
            sm.wt[r][tx] = W[(size_t)(k0 + r) * DMODEL + n0 + tx];
        __syncthreads();
        for (int r = ty; r < 32; r += 8) {
            float x = sm.wt[tx][r];
            __nv_bfloat16 hi = __float2bfloat16(x);
            size_t o = (size_t)(n0 + r) * DMODEL + k0 + tx;
            g_Whi[o] = hi;
            g_Wlo[o] = __float2bfloat16(x - __bfloat162float(hi));
        }
    } else if (bid < 1568) {
        int t = bid - 1536;
        int h = t & 15, b = t >> 4;
        for (int j = tid; j < L; j += 256) sm.hist[j] = 0;
        __syncthreads();
        uint32_t hk0, hk1, s0, s1;
        threefry2x32(0u, 42u, 0u, (uint32_t)h, hk0, hk1);
        threefry2x32(hk0, hk1, 0u, 1u, s0, s1);
        for (int i = tid; i < USAMP; i += 256) {
            uint32_t b1, b2;
            threefry2x32(s0, s1, 0u, (uint32_t)(b * USAMP + i), b1, b2);
            atomicAdd(&sm.hist[(b1 ^ b2) & 1023u], 1u);
        }
        __syncthreads();
        for (int j = tid; j < L; j += 256)
            g_cnt8[b][j][h] = (uint8_t)sm.hist[j];
    } else {
        int b = bid - 1568;
        int d = tid & 63, g = tid >> 6;
        float s = 0.f;
        for (int kk = g; kk < L; kk += 4)
            s += v[((size_t)b * L + kk) * D + d];
        sm.part[tid] = s;
        __syncthreads();
        if (tid < 64)
            g_meanv[b][tid] = (sm.part[tid] + sm.part[tid + 64] + sm.part[tid + 128] + sm.part[tid + 192]) * (1.0f / 1024.0f);
    }
}

// ================= K2: fused measure (all 16 heads, one S pass) + fill =================
__global__ void __launch_bounds__(256) k_measure_fill() {
    int bid = blockIdx.x;
    int tid = threadIdx.x;
    if (bid < 256) {
        int wid = tid >> 5, lane = tid & 31;
        int rowg = bid * 8 + wid;
        int b = rowg >> 10, row = rowg & 1023;
        const float* Srow = g_S[b][row];
        float mx[16], sv[16];
#pragma unroll
        for (int h = 0; h < 16; h++) { mx[h] = -3.4e38f; sv[h] = 0.f; }
        for (int j = lane; j < L; j += 32) {
            float s = Srow[j];
            uint4 c16 = *(const uint4*)&g_cnt8[b][j][0];
#define HP(wrd, base) { \
            int c0 = (wrd) & 255, c1 = ((wrd) >> 8) & 255, c2 = ((wrd) >> 16) & 255, c3 = (int)((wrd) >> 24); \
            if (c0) mx[(base)]     = fmaxf(mx[(base)],     s);  sv[(base)]     += (float)c0 * s; \
            if (c1) mx[(base) + 1] = fmaxf(mx[(base) + 1], s);  sv[(base) + 1] += (float)c1 * s; \
            if (c2) mx[(base) + 2] = fmaxf(mx[(base) + 2], s);  sv[(base) + 2] += (float)c2 * s; \
            if (c3) mx[(base) + 3] = fmaxf(mx[(base) + 3], s);  sv[(base) + 3] += (float)c3 * s; }
            HP(c16.x, 0) HP(c16.y, 4) HP(c16.z, 8) HP(c16.w, 12)
#undef HP
        }
#pragma unroll
        for (int h = 0; h < 16; h++) {
            float m = mx[h], s = sv[h];
#pragma unroll
            for (int off = 16; off; off >>= 1) {
                m = fmaxf(m, __shfl_down_sync(0xffffffffu, m, off));
                s += __shfl_down_sync(0xffffffffu, s, off);
            }
            if (lane == 0) g_M[b][h][row] = m - s / 7097.0f;
        }
    } else {
        int t = bid - 256;
        int base = (t * 256 + tid) * 8;
        int b = base >> 20;
#pragma unroll
        for (int e = 0; e < 8; e++) {
            int idx = base + e;
            float x = g_meanv[b][(idx & 63)];
            __nv_bfloat16 hi = __float2bfloat16(x);
            g_Ahi[idx] = hi;
            g_Alo[idx] = __float2bfloat16(x - __bfloat162float(hi));
        }
    }
}

// ================= K3: top-34 via packed-u64 shfl reduce (1024 threads) =================
__global__ void __launch_bounds__(1024) k_topk() {
    int h = blockIdx.x, b = blockIdx.y;
    int tid = threadIdx.x;
    int wid = tid >> 5, lane = tid & 31;
    __shared__ unsigned long long sk[32];

    float val = g_M[b][h][tid];
    uint32_t ub = __float_as_uint(val);
    uint32_t u = (ub & 0x80000000u) ? ~ub : (ub | 0x80000000u);
    unsigned long long key = ((unsigned long long)u << 10) | (unsigned long long)(1023 - tid);

    for (int t = 0; t < USEL; t++) {
        unsigned long long k2 = key;
#pragma unroll
        for (int off = 16; off; off >>= 1) {
            unsigned long long o = __shfl_down_sync(0xffffffffu, k2, off);
            if (o > k2) k2 = o;
        }
        if (lane == 0) sk[wid] = k2;
        __syncthreads();
        if (wid == 0) {
            unsigned long long k3 = sk[lane];
#pragma unroll
            for (int off = 16; off; off >>= 1) {
                unsigned long long o = __shfl_down_sync(0xffffffffu, k3, off);
                if (o > k3) k3 = o;
            }
            if (lane == 0) {
                sk[0] = k3;
                g_top[b][h][t] = 1023 - (int)(k3 & 1023ull);
            }
        }
        __syncthreads();
        int widx = 1023 - (int)(sk[0] & 1023ull);
        if (tid == widx) key = 0ull;
        __syncthreads();
    }
}

// ================= K4: softmax weights for selected rows (1088 blocks) =================
__global__ void k_softmax() {
    int i = blockIdx.x, h = blockIdx.y, b = blockIdx.z;
    int qs = g_top[b][h][i];
    __shared__ float red[256];
    int tid = threadIdx.x;
    const float* Srow = g_S[b][qs];

    float mx = -3.4e38f;
    for (int j = tid; j < L; j += 256) mx = fmaxf(mx, Srow[j]);
    red[tid] = mx;
    __syncthreads();
    for (int s = 128; s; s >>= 1) { if (tid < s) red[tid] = fmaxf(red[tid], red[tid + s]); __syncthreads(); }
    float mxs = red[0] * 0.03125f;
    __syncthreads();

    float sum = 0.f;
    float* Prow = g_P[b][h][i];
    for (int j = tid; j < L; j += 256) {
        float e = __expf(Srow[j] * 0.03125f - mxs);
        Prow[j] = e;
        sum += e;
    }
    red[tid] = sum;
    __syncthreads();
    for (int s = 128; s; s >>= 1) { if (tid < s) red[tid] += red[tid + s]; __syncthreads(); }
    if (tid == 0) g_rs[b][h][i] = 1.0f / red[0];
}

// ================= K5: PV partials (v slice cached in smem) =================
__global__ void k_pv(const float* __restrict__ v) {
    __shared__ float vs[CHK][64];
    __shared__ float ps[USEL][CHK];
    int ch = blockIdx.x, h = blockIdx.y, b = blockIdx.z;
    int k0 = ch * CHK;
    int tid = threadIdx.x;

    for (int u = tid; u < CHK * 64 / 4; u += 256) {
        int kk = u >> 4, c4 = (u & 15) * 4;
        *(float4*)&vs[kk][c4] = *(const float4*)&v[((size_t)b * L + k0 + kk) * D + c4];
    }
    for (int u = tid; u < USEL * CHK / 4; u += 256) {
        int row = u / (CHK / 4), c4 = (u % (CHK / 4)) * 4;
        *(float4*)&ps[row][c4] = *(const float4*)&g_P[b][h][row][k0 + c4];
    }
    __syncthreads();

    int r = tid >> 6, d = tid & 63;
    float acc[9];
#pragma unroll
    for (int i = 0; i < 9; i++) acc[i] = 0.f;

    for (int kk = 0; kk < CHK; kk += 4) {
        float v0 = vs[kk][d], v1 = vs[kk + 1][d], v2 = vs[kk + 2][d], v3 = vs[kk + 3][d];
#pragma unroll
        for (int i = 0; i < 9; i++) {
            int row = r + i * 4;
            if (row < USEL) {
                float4 p4 = *(float4*)&ps[row][kk];
                acc[i] += p4.x * v0 + p4.y * v1 + p4.z * v2 + p4.w * v3;
            }
        }
    }
#pragma unroll
    for (int i = 0; i < 9; i++) {
        int row = r + i * 4;
        if (row < USEL)
            g_pacc[b][h][row][ch][d] = acc[i];
    }
}

// ================= K6: sum partials, normalize, write bf16 split rows =================
__global__ void k_write() {
    int bh = blockIdx.x;
    int b = bh >> 4, h = bh & 15;
    int tid = threadIdx.x;
    int r = tid >> 6, d = tid & 63;
    for (int row = r; row < USEL; row += 4) {
        float s = 0.f;
#pragma unroll
        for (int c = 0; c < NCH; c++) s += g_pacc[b][h][row][c][d];
        float val = s * g_rs[b][h][row];
        int qs = g_top[b][h][row];
        size_t idx = (size_t)(b * L + qs) * DMODEL + h * D + d;
        __nv_bfloat16 hi = __float2bfloat16(val);
        g_Ahi[idx] = hi;
        g_Alo[idx] = __float2bfloat16(val - __bfloat162float(hi));
    }
}

// ================= K7: wmma GEMM (KC=32, stride SPAD=40 -> conflict-free LDSM) =================
__device__ __forceinline__ void load_stage(__nv_bfloat16* s, int bm, int bn, int k0, int tid) {
    for (int u = tid; u < 512; u += 256) {
        int row = u >> 2, c = (u & 3) * 8;
        size_t ga = (size_t)(bm + row) * DMODEL + k0 + c;
        size_t gb = (size_t)(bn + row) * DMODEL + k0 + c;
        int so = row * SPAD + c;
        *(uint4*)&s[so]            = *(const uint4*)&g_Ahi[ga];
        *(uint4*)&s[TILE + so]     = *(const uint4*)&g_Alo[ga];
        *(uint4*)&s[2 * TILE + so] = *(const uint4*)&g_Whi[gb];
        *(uint4*)&s[3 * TILE + so] = *(const uint4*)&g_Wlo[gb];
    }
}

__global__ void __launch_bounds__(256, 1) k_proj_wmma(const float* __restrict__ bias,
                                                      float* __restrict__ out) {
    extern __shared__ __nv_bfloat16 sm[];
    int tid = threadIdx.x;
    int w = tid >> 5;
    int wm = w & 1;
    int wn = w >> 1;
    int bm = blockIdx.y * 128, bn = blockIdx.x * 128;

    wmma::fragment<wmma::accumulator, 16, 16, 16, float> acc[4][2];
#pragma unroll
    for (int i = 0; i < 4; i++)
#pragma unroll
        for (int j = 0; j < 2; j++)
            wmma::fill_fragment(acc[i][j], 0.0f);

    load_stage(sm, bm, bn, 0, tid);
    __syncthreads();

    for (int c = 0; c < DMODEL / KC; c++) {
        int cur = c & 1;
        if (c + 1 < DMODEL / KC)
            load_stage(sm + (cur ^ 1) * 4 * TILE, bm, bn, (c + 1) * KC, tid);

        const __nv_bfloat16* s   = sm + cur * 4 * TILE;
        const __nv_bfloat16* Ahi = s;
        const __nv_bfloat16* Alo = s + TILE;
        const __nv_bfloat16* Bhi = s + 2 * TILE;
        const __nv_bfloat16* Blo = s + 3 * TILE;
#pragma unroll
        for (int kk = 0; kk < KC; kk += 16) {
            wmma::fragment<wmma::matrix_a, 16, 16, 16, __nv_bfloat16, wmma::row_major> ah[4], al[4];
            wmma::fragment<wmma::matrix_b, 16, 16, 16, __nv_bfloat16, wmma::col_major> bh[2], bl[2];
#pragma unroll
            for (int i = 0; i < 4; i++) {
                wmma::load_matrix_sync(ah[i], Ahi + (wm * 64 + i * 16) * SPAD + kk, SPAD);
                wmma::load_matrix_sync(al[i], Alo + (wm * 64 + i * 16) * SPAD + kk, SPAD);
            }
#pragma unroll
            for (int j = 0; j < 2; j++) {
                wmma::load_matrix_sync(bh[j], Bhi + (wn * 32 + j * 16) * SPAD + kk, SPAD);
                wmma::load_matrix_sync(bl[j], Blo + (wn * 32 + j * 16) * SPAD + kk, SPAD);
            }
#pragma unroll
            for (int i = 0; i < 4; i++)
#pragma unroll
                for (int j = 0; j < 2; j++) {
                    wmma::mma_sync(acc[i][j], ah[i], bh[j], acc[i][j]);
                    wmma::mma_sync(acc[i][j], ah[i], bl[j], acc[i][j]);
                    wmma::mma_sync(acc[i][j], al[i], bh[j], acc[i][j]);
                }
        }
        __syncthreads();
    }

    float* fs = (float*)sm;
#pragma unroll
    for (int i = 0; i < 4; i++)
#pragma unroll
        for (int j = 0; j < 2; j++)
            wmma::store_matrix_sync(&fs[(wm * 64 + i * 16) * 128 + wn * 32 + j * 16],
                                    acc[i][j], 128, wmma::mem_row_major);
    __syncthreads();
    for (int u = tid; u < 128 * 128 / 4; u += 256) {
        int row = u >> 5, c4 = (u & 31) * 4;
        float4 vv = *(float4*)&fs[row * 128 + c4];
        float4 bb = *(const float4*)&bias[bn + c4];
        vv.x += bb.x; vv.y += bb.y; vv.z += bb.z; vv.w += bb.w;
        *(float4*)&out[(size_t)(bm + row) * DMODEL + bn + c4] = vv;
    }
}

// ---------------- launch ----------------
extern "C" void kernel_launch(void* const* d_in, const int* in_sizes, int n_in,
                              void* d_out, int out_size) {
    const float* q    = (const float*)d_in[0];
    const float* k    = (const float*)d_in[1];
    const float* v    = (const float*)d_in[2];
    const float* W    = (const float*)d_in[3];
    const float* bias = (const float*)d_in[4];
    float* out = (float*)d_out;

    cudaFuncSetAttribute(k_proj_wmma, cudaFuncAttributeMaxDynamicSharedMemorySize, SMEM_DYN);

    k_mega<<<1570, 256>>>(q, k, v, W);

    k_measure_fill<<<256 + 1024, 256>>>();

    dim3 gT(H_HEADS, BATCH);
    k_topk<<<gT, 1024>>>();

    dim3 gSm(USEL, H_HEADS, BATCH);
    k_softmax<<<gSm, 256>>>();

    dim3 gPV(NCH, H_HEADS, BATCH);
    k_pv<<<gPV, 256>>>(v);

    k_write<<<BATCH * H_HEADS, 256>>>();

    dim3 gG(DMODEL / 128, MROWS / 128);
    k_proj_wmma<<<gG, 256, SMEM_DYN>>>(bias, out);
}

// round 8
// speedup vs baseline: 1.9061x; 1.2704x over previous
#include <cuda_runtime.h>
#include <cstdint>
#include <math.h>

// Problem constants
#define H_HEADS 16
#define BATCH   2
#define L       1024
#define D       64
#define USAMP   7097
#define USEL    34
#define DMODEL  (H_HEADS * D)   // 1024
#define MROWS   (BATCH * L)     // 2048

// PV tiling
#define NCH 16
#define CHK 64

// ---------------- scratch (static device globals; no allocation) ----------------
__device__ float g_S[BATCH][L][L];
__device__ uint8_t g_cnt8[BATCH][L][16];
__device__ float g_M[BATCH][H_HEADS][L];
__device__ int   g_top[BATCH][H_HEADS][USEL];
__device__ int   g_sel[BATCH][H_HEADS][L];     // q -> selection index (or -1)
__device__ float g_meanv[BATCH][D];
__device__ float g_P[BATCH][H_HEADS][USEL][L];
__device__ float g_rs[BATCH][H_HEADS][USEL];
__device__ float g_pacc[BATCH][H_HEADS][USEL][NCH][64];
__device__ float g_delta[BATCH][H_HEADS][USEL][D];      // s1 - meanv
__device__ float g_E[BATCH][H_HEADS][USEL][DMODEL];     // delta @ W_h
__device__ float g_base[BATCH][DMODEL];                 // meanv_full @ W + bias

// ---------------- threefry2x32 (JAX-compatible) ----------------
__device__ __forceinline__ uint32_t rotl32(uint32_t x, int d) {
    return (x << d) | (x >> (32 - d));
}

__device__ __forceinline__ void threefry2x32(uint32_t k0, uint32_t k1,
                                             uint32_t x0, uint32_t x1,
                                             uint32_t& o0, uint32_t& o1) {
    uint32_t ks2 = k0 ^ k1 ^ 0x1BD11BDAu;
    x0 += k0; x1 += k1;
#define TFR(r) { x0 += x1; x1 = rotl32(x1, (r)); x1 ^= x0; }
    TFR(13) TFR(15) TFR(26) TFR(6)   x0 += k1;  x1 += ks2 + 1u;
    TFR(17) TFR(29) TFR(16) TFR(24)  x0 += ks2; x1 += k0 + 2u;
    TFR(13) TFR(15) TFR(26) TFR(6)   x0 += k0;  x1 += k1 + 3u;
    TFR(17) TFR(29) TFR(16) TFR(24)  x0 += k1;  x1 += ks2 + 4u;
    TFR(13) TFR(15) TFR(26) TFR(6)   x0 += ks2; x1 += k0 + 5u;
#undef TFR
    o0 = x0; o1 = x1;
}

// ================= K1: mega prologue (scores | idx hist | meanv | sel-init) =================
__global__ void __launch_bounds__(256) k_mega(const float* __restrict__ q,
                                              const float* __restrict__ k,
                                              const float* __restrict__ v) {
    __shared__ union {
        struct { float qs[64][65]; float ks[64][65]; } sc;
        uint32_t hist[L];
        float part[256];
    } sm;
    int bid = blockIdx.x;
    int tid = threadIdx.x;

    if (bid < 512) {
        // ---- scores: S[b] = q[b] @ k[b]^T ----
        int b  = bid >> 8;
        int i0 = ((bid >> 4) & 15) * 64, j0 = (bid & 15) * 64;
        for (int t = tid; t < 4096; t += 256) {
            int r = t >> 6, c = t & 63;
            sm.sc.qs[r][c] = q[((size_t)b * L + i0 + r) * D + c];
            sm.sc.ks[r][c] = k[((size_t)b * L + j0 + r) * D + c];
        }
        __syncthreads();
        int tx = tid & 15, ty = tid >> 4;
        float acc[4][4] = {};
#pragma unroll 8
        for (int d = 0; d < 64; d++) {
            float a[4], bb[4];
#pragma unroll
            for (int r = 0; r < 4; r++) a[r] = sm.sc.qs[ty * 4 + r][d];
#pragma unroll
            for (int c = 0; c < 4; c++) bb[c] = sm.sc.ks[tx * 4 + c][d];
#pragma unroll
            for (int r = 0; r < 4; r++)
#pragma unroll
                for (int c = 0; c < 4; c++)
                    acc[r][c] += a[r] * bb[c];
        }
#pragma unroll
        for (int r = 0; r < 4; r++)
#pragma unroll
            for (int c = 0; c < 4; c++)
                g_S[b][i0 + ty * 4 + r][j0 + tx * 4 + c] = acc[r][c];
    } else if (bid < 544) {
        // ---- sampled-index histogram for one (h, b), smem counters ----
        int t = bid - 512;
        int h = t & 15, b = t >> 4;
        for (int j = tid; j < L; j += 256) sm.hist[j] = 0;
        __syncthreads();
        uint32_t hk0, hk1, s0, s1;
        threefry2x32(0u, 42u, 0u, (uint32_t)h, hk0, hk1);
        threefry2x32(hk0, hk1, 0u, 1u, s0, s1);
        for (int i = tid; i < USAMP; i += 256) {
            uint32_t b1, b2;
            threefry2x32(s0, s1, 0u, (uint32_t)(b * USAMP + i), b1, b2);
            atomicAdd(&sm.hist[(b1 ^ b2) & 1023u], 1u);
        }
        __syncthreads();
        for (int j = tid; j < L; j += 256)
            g_cnt8[b][j][h] = (uint8_t)sm.hist[j];
    } else if (bid < 546) {
        // ---- meanv ----
        int b = bid - 544;
        int d = tid & 63, g = tid >> 6;
        float s = 0.f;
        for (int kk = g; kk < L; kk += 4)
            s += v[((size_t)b * L + kk) * D + d];
        sm.part[tid] = s;
        __syncthreads();
        if (tid < 64)
            g_meanv[b][tid] = (sm.part[tid] + sm.part[tid + 64] + sm.part[tid + 128] + sm.part[tid + 192]) * (1.0f / 1024.0f);
    } else {
        // ---- g_sel init to -1 : 8 blocks x 256 threads x 16 ints ----
        int t = bid - 546;
        int base = (t * 256 + tid) * 16;
        int* sp = &g_sel[0][0][0];
#pragma unroll
        for (int e = 0; e < 16; e++) sp[base + e] = -1;
    }
}

// ================= K2: fused measure (all 16 heads, one S pass) + base GEMV =================
__global__ void __launch_bounds__(256) k_measure_base(const float* __restrict__ W,
                                                      const float* __restrict__ bias) {
    int bid = blockIdx.x;
    int tid = threadIdx.x;
    if (bid < 256) {
        int wid = tid >> 5, lane = tid & 31;
        int rowg = bid * 8 + wid;
        int b = rowg >> 10, row = rowg & 1023;
        const float* Srow = g_S[b][row];
        float mx[16], sv[16];
#pragma unroll
        for (int h = 0; h < 16; h++) { mx[h] = -3.4e38f; sv[h] = 0.f; }
        for (int j = lane; j < L; j += 32) {
            float s = Srow[j];
            uint4 c16 = *(const uint4*)&g_cnt8[b][j][0];
#define HP(wrd, base) { \
            int c0 = (wrd) & 255, c1 = ((wrd) >> 8) & 255, c2 = ((wrd) >> 16) & 255, c3 = (int)((wrd) >> 24); \
            if (c0) mx[(base)]     = fmaxf(mx[(base)],     s);  sv[(base)]     += (float)c0 * s; \
            if (c1) mx[(base) + 1] = fmaxf(mx[(base) + 1], s);  sv[(base) + 1] += (float)c1 * s; \
            if (c2) mx[(base) + 2] = fmaxf(mx[(base) + 2], s);  sv[(base) + 2] += (float)c2 * s; \
            if (c3) mx[(base) + 3] = fmaxf(mx[(base) + 3], s);  sv[(base) + 3] += (float)c3 * s; }
            HP(c16.x, 0) HP(c16.y, 4) HP(c16.z, 8) HP(c16.w, 12)
#undef HP
        }
#pragma unroll
        for (int h = 0; h < 16; h++) {
            float m = mx[h], s = sv[h];
#pragma unroll
            for (int off = 16; off; off >>= 1) {
                m = fmaxf(m, __shfl_down_sync(0xffffffffu, m, off));
                s += __shfl_down_sync(0xffffffffu, s, off);
            }
            if (lane == 0) g_M[b][h][row] = m - s / 7097.0f;
        }
    } else {
        // ---- base GEMV: g_base[b][c] = sum_k meanv[b][k&63] * W[k][c] + bias[c] ----
        int t = bid - 256;          // 0..7
        int b = t >> 2;
        int c = (t & 3) * 256 + tid;
        __shared__ float mv[64];
        if (tid < 64) mv[tid] = g_meanv[b][tid];
        __syncthreads();
        float acc = 0.f;
#pragma unroll 4
        for (int k = 0; k < DMODEL; k++)
            acc += mv[k & 63] * W[(size_t)k * DMODEL + c];
        g_base[b][c] = acc + bias[c];
    }
}

// ================= K3: top-34 via packed-u64 shfl reduce + write g_sel =================
__global__ void __launch_bounds__(1024) k_topk() {
    int h = blockIdx.x, b = blockIdx.y;
    int tid = threadIdx.x;
    int wid = tid >> 5, lane = tid & 31;
    __shared__ unsigned long long sk[32];

    float val = g_M[b][h][tid];
    uint32_t ub = __float_as_uint(val);
    uint32_t u = (ub & 0x80000000u) ? ~ub : (ub | 0x80000000u);
    unsigned long long key = ((unsigned long long)u << 10) | (unsigned long long)(1023 - tid);

    for (int t = 0; t < USEL; t++) {
        unsigned long long k2 = key;
#pragma unroll
        for (int off = 16; off; off >>= 1) {
            unsigned long long o = __shfl_down_sync(0xffffffffu, k2, off);
            if (o > k2) k2 = o;
        }
        if (lane == 0) sk[wid] = k2;
        __syncthreads();
        if (wid == 0) {
            unsigned long long k3 = sk[lane];
#pragma unroll
            for (int off = 16; off; off >>= 1) {
                unsigned long long o = __shfl_down_sync(0xffffffffu, k3, off);
                if (o > k3) k3 = o;
            }
            if (lane == 0) {
                sk[0] = k3;
                int widx = 1023 - (int)(k3 & 1023ull);
                g_top[b][h][t] = widx;
                g_sel[b][h][widx] = t;
            }
        }
        __syncthreads();
        int widx = 1023 - (int)(sk[0] & 1023ull);
        if (tid == widx) key = 0ull;
        __syncthreads();
    }
}

// ================= K4: softmax weights for selected rows =================
__global__ void k_softmax() {
    int i = blockIdx.x, h = blockIdx.y, b = blockIdx.z;
    int qs = g_top[b][h][i];
    __shared__ float red[256];
    int tid = threadIdx.x;
    const float* Srow = g_S[b][qs];

    float mx = -3.4e38f;
    for (int j = tid; j < L; j += 256) mx = fmaxf(mx, Srow[j]);
    red[tid] = mx;
    __syncthreads();
    for (int s = 128; s; s >>= 1) { if (tid < s) red[tid] = fmaxf(red[tid], red[tid + s]); __syncthreads(); }
    float mxs = red[0] * 0.03125f;
    __syncthreads();

    float sum = 0.f;
    float* Prow = g_P[b][h][i];
    for (int j = tid; j < L; j += 256) {
        float e = __expf(Srow[j] * 0.03125f - mxs);
        Prow[j] = e;
        sum += e;
    }
    red[tid] = sum;
    __syncthreads();
    for (int s = 128; s; s >>= 1) { if (tid < s) red[tid] += red[tid + s]; __syncthreads(); }
    if (tid == 0) g_rs[b][h][i] = 1.0f / red[0];
}

// ================= K5: PV partials (v slice cached in smem) =================
__global__ void k_pv(const float* __restrict__ v) {
    __shared__ float vs[CHK][64];
    __shared__ float ps[USEL][CHK];
    int ch = blockIdx.x, h = blockIdx.y, b = blockIdx.z;
    int k0 = ch * CHK;
    int tid = threadIdx.x;

    for (int u = tid; u < CHK * 64 / 4; u += 256) {
        int kk = u >> 4, c4 = (u & 15) * 4;
        *(float4*)&vs[kk][c4] = *(const float4*)&v[((size_t)b * L + k0 + kk) * D + c4];
    }
    for (int u = tid; u < USEL * CHK / 4; u += 256) {
        int row = u / (CHK / 4), c4 = (u % (CHK / 4)) * 4;
        *(float4*)&ps[row][c4] = *(const float4*)&g_P[b][h][row][k0 + c4];
    }
    __syncthreads();

    int r = tid >> 6, d = tid & 63;
    float acc[9];
#pragma unroll
    for (int i = 0; i < 9; i++) acc[i] = 0.f;

    for (int kk = 0; kk < CHK; kk += 4) {
        float v0 = vs[kk][d], v1 = vs[kk + 1][d], v2 = vs[kk + 2][d], v3 = vs[kk + 3][d];
#pragma unroll
        for (int i = 0; i < 9; i++) {
            int row = r + i * 4;
            if (row < USEL) {
                float4 p4 = *(float4*)&ps[row][kk];
                acc[i] += p4.x * v0 + p4.y * v1 + p4.z * v2 + p4.w * v3;
            }
        }
    }
#pragma unroll
    for (int i = 0; i < 9; i++) {
        int row = r + i * 4;
        if (row < USEL)
            g_pacc[b][h][row][ch][d] = acc[i];
    }
}

// ================= K6: delta = s1 - meanv =================
__global__ void k_delta() {
    int bh = blockIdx.x;
    int b = bh >> 4, h = bh & 15;
    int tid = threadIdx.x;
    int r = tid >> 6, d = tid & 63;
    for (int row = r; row < USEL; row += 4) {
        float s = 0.f;
#pragma unroll
        for (int c = 0; c < NCH; c++) s += g_pacc[b][h][row][c][d];
        g_delta[b][h][row][d] = s * g_rs[b][h][row] - g_meanv[b][d];
    }
}

// ================= K7: correction GEMM  E[b][h] = delta[b][h] @ W[h*64:(h+1)*64, :] =================
__global__ void __launch_bounds__(128) k_corr(const float* __restrict__ W) {
    __shared__ float sd[USEL][64];
    int nc = blockIdx.x;            // 0..7 -> 128-col chunk
    int h  = blockIdx.y, b = blockIdx.z;
    int tid = threadIdx.x;          // 128 threads
    int n0 = nc * 128;

    for (int u = tid; u < USEL * 64 / 2; u += 128) {
        int row = u >> 5, c2 = (u & 31) * 2;
        *(float2*)&sd[row][c2] = *(const float2*)&g_delta[b][h][row][c2];
    }
    __syncthreads();

    float acc[USEL];
#pragma unroll
    for (int i = 0; i < USEL; i++) acc[i] = 0.f;

    const float* Wp = W + (size_t)(h * 64) * DMODEL + n0 + tid;
#pragma unroll 4
    for (int k = 0; k < 64; k++) {
        float w = Wp[(size_t)k * DMODEL];
#pragma unroll
        for (int i = 0; i < USEL; i++)
            acc[i] += sd[i][k] * w;
    }
#pragma unroll
    for (int i = 0; i < USEL; i++)
        g_E[b][h][i][n0 + tid] = acc[i];
}

// ================= K8: assemble out = base + sum of selected corrections =================
__global__ void __launch_bounds__(256) k_out(float* __restrict__ out) {
    __shared__ int sel[16];
    int bid = blockIdx.x;
    int b = bid >> 10, qq = bid & 1023;
    int tid = threadIdx.x;
    if (tid < 16) sel[tid] = g_sel[b][tid][qq];
    __syncthreads();

    int c4 = tid * 4;
    float4 val = *(const float4*)&g_base[b][c4];
#pragma unroll
    for (int h = 0; h < 16; h++) {
        int i = sel[h];
        if (i >= 0) {
            float4 e = *(const float4*)&g_E[b][h][i][c4];
            val.x += e.x; val.y += e.y; val.z += e.z; val.w += e.w;
        }
    }
    *(float4*)&out[(size_t)(b * L + qq) * DMODEL + c4] = val;
}

// ---------------- launch ----------------
extern "C" void kernel_launch(void* const* d_in, const int* in_sizes, int n_in,
                              void* d_out, int out_size) {
    const float* q    = (const float*)d_in[0];
    const float* k    = (const float*)d_in[1];
    const float* v    = (const float*)d_in[2];
    const float* W    = (const float*)d_in[3];
    const float* bias = (const float*)d_in[4];
    float* out = (float*)d_out;

    k_mega<<<554, 256>>>(q, k, v);

    k_measure_base<<<264, 256>>>(W, bias);

    dim3 gT(H_HEADS, BATCH);
    k_topk<<<gT, 1024>>>();

    dim3 gSm(USEL, H_HEADS, BATCH);
    k_softmax<<<gSm, 256>>>();

    dim3 gPV(NCH, H_HEADS, BATCH);
    k_pv<<<gPV, 256>>>(v);

    k_delta<<<BATCH * H_HEADS, 256>>>();

    dim3 gC(8, H_HEADS, BATCH);
    k_corr<<<gC, 128>>>(W);

    k_out<<<MROWS, 256>>>(out);
}

// round 9
// speedup vs baseline: 2.6648x; 1.3981x over previous
#include <cuda_runtime.h>
#include <cstdint>
#include <math.h>

// Problem constants
#define H_HEADS 16
#define BATCH   2
#define L       1024
#define D       64
#define USAMP   7097
#define USEL    34
#define DMODEL  (H_HEADS * D)   // 1024
#define MROWS   (BATCH * L)     // 2048

// PV tiling
#define NCH 32
#define CHK 32

// ---------------- scratch (static device globals; no allocation) ----------------
__device__ float g_S[BATCH][L][L];
__device__ uint8_t g_cnt8[BATCH][L][16];
__device__ float g_M[BATCH][H_HEADS][L];
__device__ int   g_top[BATCH][H_HEADS][USEL];
__device__ int   g_sel[BATCH][H_HEADS][L];     // q -> selection index (or -1)
__device__ float g_meanv[BATCH][D];
__device__ float g_pacc[BATCH][H_HEADS][USEL][NCH][64];  // per-chunk PV partials (unnormalized)
__device__ float g_psum[BATCH][H_HEADS][USEL][NCH];      // per-chunk exp row sums
__device__ float g_delta[BATCH][H_HEADS][USEL][D];       // s1 - meanv
__device__ float g_E[BATCH][H_HEADS][USEL][DMODEL];      // delta @ W_h
__device__ float g_base[BATCH][DMODEL];                  // meanv_full @ W + bias

// ---------------- threefry2x32 (JAX-compatible) ----------------
__device__ __forceinline__ uint32_t rotl32(uint32_t x, int d) {
    return (x << d) | (x >> (32 - d));
}

__device__ __forceinline__ void threefry2x32(uint32_t k0, uint32_t k1,
                                             uint32_t x0, uint32_t x1,
                                             uint32_t& o0, uint32_t& o1) {
    uint32_t ks2 = k0 ^ k1 ^ 0x1BD11BDAu;
    x0 += k0; x1 += k1;
#define TFR(r) { x0 += x1; x1 = rotl32(x1, (r)); x1 ^= x0; }
    TFR(13) TFR(15) TFR(26) TFR(6)   x0 += k1;  x1 += ks2 + 1u;
    TFR(17) TFR(29) TFR(16) TFR(24)  x0 += ks2; x1 += k0 + 2u;
    TFR(13) TFR(15) TFR(26) TFR(6)   x0 += k0;  x1 += k1 + 3u;
    TFR(17) TFR(29) TFR(16) TFR(24)  x0 += k1;  x1 += ks2 + 4u;
    TFR(13) TFR(15) TFR(26) TFR(6)   x0 += ks2; x1 += k0 + 5u;
#undef TFR
    o0 = x0; o1 = x1;
}

// ================= K1: mega prologue (scores | hist | meanv | sel-init | base-init) =================
__global__ void __launch_bounds__(256) k_mega(const float* __restrict__ q,
                                              const float* __restrict__ k,
                                              const float* __restrict__ v,
                                              const float* __restrict__ bias) {
    __shared__ union {
        struct { float qs[64][65]; float ks[64][65]; } sc;
        uint32_t hist[L];
        float part[256];
    } sm;
    int bid = blockIdx.x;
    int tid = threadIdx.x;

    if (bid < 512) {
        // ---- scores: S[b] = q[b] @ k[b]^T ----
        int b  = bid >> 8;
        int i0 = ((bid >> 4) & 15) * 64, j0 = (bid & 15) * 64;
        for (int t = tid; t < 4096; t += 256) {
            int r = t >> 6, c = t & 63;
            sm.sc.qs[r][c] = q[((size_t)b * L + i0 + r) * D + c];
            sm.sc.ks[r][c] = k[((size_t)b * L + j0 + r) * D + c];
        }
        __syncthreads();
        int tx = tid & 15, ty = tid >> 4;
        float acc[4][4] = {};
#pragma unroll 8
        for (int d = 0; d < 64; d++) {
            float a[4], bb[4];
#pragma unroll
            for (int r = 0; r < 4; r++) a[r] = sm.sc.qs[ty * 4 + r][d];
#pragma unroll
            for (int c = 0; c < 4; c++) bb[c] = sm.sc.ks[tx * 4 + c][d];
#pragma unroll
            for (int r = 0; r < 4; r++)
#pragma unroll
                for (int c = 0; c < 4; c++)
                    acc[r][c] += a[r] * bb[c];
        }
#pragma unroll
        for (int r = 0; r < 4; r++)
#pragma unroll
            for (int c = 0; c < 4; c++)
                g_S[b][i0 + ty * 4 + r][j0 + tx * 4 + c] = acc[r][c];
    } else if (bid < 544) {
        // ---- sampled-index histogram for one (h, b) ----
        int t = bid - 512;
        int h = t & 15, b = t >> 4;
        for (int j = tid; j < L; j += 256) sm.hist[j] = 0;
        __syncthreads();
        uint32_t hk0, hk1, s0, s1;
        threefry2x32(0u, 42u, 0u, (uint32_t)h, hk0, hk1);
        threefry2x32(hk0, hk1, 0u, 1u, s0, s1);
        for (int i = tid; i < USAMP; i += 256) {
            uint32_t b1, b2;
            threefry2x32(s0, s1, 0u, (uint32_t)(b * USAMP + i), b1, b2);
            atomicAdd(&sm.hist[(b1 ^ b2) & 1023u], 1u);
        }
        __syncthreads();
        for (int j = tid; j < L; j += 256)
            g_cnt8[b][j][h] = (uint8_t)sm.hist[j];
    } else if (bid < 546) {
        // ---- meanv ----
        int b = bid - 544;
        int d = tid & 63, g = tid >> 6;
        float s = 0.f;
        for (int kk = g; kk < L; kk += 4)
            s += v[((size_t)b * L + kk) * D + d];
        sm.part[tid] = s;
        __syncthreads();
        if (tid < 64)
            g_meanv[b][tid] = (sm.part[tid] + sm.part[tid + 64] + sm.part[tid + 128] + sm.part[tid + 192]) * (1.0f / 1024.0f);
    } else if (bid < 554) {
        // ---- g_sel init to -1 ----
        int t = bid - 546;
        int base = (t * 256 + tid) * 16;
        int* sp = &g_sel[0][0][0];
#pragma unroll
        for (int e = 0; e < 16; e++) sp[base + e] = -1;
    } else {
        // ---- g_base init with bias ----
        int b = bid - 554;
        int c4 = tid * 4;
        *(float4*)&g_base[b][c4] = *(const float4*)&bias[c4];
    }
}

// ================= K2: base GEMV (blocks 0-7, first wave) + fused measure =================
__global__ void __launch_bounds__(256) k_measure_base(const float* __restrict__ W) {
    int bid = blockIdx.x;
    int tid = threadIdx.x;
    if (bid < 8) {
        // ---- base GEMV partial: b = bid>>2, col chunk = (bid&3)*256 + tid, full K ----
        int b = bid >> 2;
        int c = (bid & 3) * 256 + tid;
        __shared__ float mv[64];
        if (tid < 64) mv[tid] = g_meanv[0][tid + ((b) ? 64 : 0) * 0];  // placeholder; fixed below
        // correct load (avoid compiler confusion):
        __syncthreads();
        if (tid < 64) mv[tid] = g_meanv[b][tid];
        __syncthreads();
        float a0 = 0.f, a1 = 0.f, a2 = 0.f, a3 = 0.f, a4 = 0.f, a5 = 0.f, a6 = 0.f, a7 = 0.f;
        for (int k = 0; k < DMODEL; k += 8) {
            a0 += mv[(k)     & 63] * W[(size_t)(k)     * DMODEL + c];
            a1 += mv[(k + 1) & 63] * W[(size_t)(k + 1) * DMODEL + c];
            a2 += mv[(k + 2) & 63] * W[(size_t)(k + 2) * DMODEL + c];
            a3 += mv[(k + 3) & 63] * W[(size_t)(k + 3) * DMODEL + c];
            a4 += mv[(k + 4) & 63] * W[(size_t)(k + 4) * DMODEL + c];
            a5 += mv[(k + 5) & 63] * W[(size_t)(k + 5) * DMODEL + c];
            a6 += mv[(k + 6) & 63] * W[(size_t)(k + 6) * DMODEL + c];
            a7 += mv[(k + 7) & 63] * W[(size_t)(k + 7) * DMODEL + c];
        }
        g_base[b][c] += ((a0 + a1) + (a2 + a3)) + ((a4 + a5) + (a6 + a7));
    } else {
        // ---- fused measure: all 16 heads in one S pass ----
        int mb = bid - 8;
        int wid = tid >> 5, lane = tid & 31;
        int rowg = mb * 8 + wid;
        int b = rowg >> 10, row = rowg & 1023;
        const float* Srow = g_S[b][row];
        float mx[16], sv[16];
#pragma unroll
        for (int h = 0; h < 16; h++) { mx[h] = -3.4e38f; sv[h] = 0.f; }
        for (int j = lane; j < L; j += 32) {
            float s = Srow[j];
            uint4 c16 = *(const uint4*)&g_cnt8[b][j][0];
#define HP(wrd, base) { \
            int c0 = (wrd) & 255, c1 = ((wrd) >> 8) & 255, c2 = ((wrd) >> 16) & 255, c3 = (int)((wrd) >> 24); \
            if (c0) mx[(base)]     = fmaxf(mx[(base)],     s);  sv[(base)]     += (float)c0 * s; \
            if (c1) mx[(base) + 1] = fmaxf(mx[(base) + 1], s);  sv[(base) + 1] += (float)c1 * s; \
            if (c2) mx[(base) + 2] = fmaxf(mx[(base) + 2], s);  sv[(base) + 2] += (float)c2 * s; \
            if (c3) mx[(base) + 3] = fmaxf(mx[(base) + 3], s);  sv[(base) + 3] += (float)c3 * s; }
            HP(c16.x, 0) HP(c16.y, 4) HP(c16.z, 8) HP(c16.w, 12)
#undef HP
        }
#pragma unroll
        for (int h = 0; h < 16; h++) {
            float m = mx[h], s = sv[h];
#pragma unroll
            for (int off = 16; off; off >>= 1) {
                m = fmaxf(m, __shfl_down_sync(0xffffffffu, m, off));
                s += __shfl_down_sync(0xffffffffu, s, off);
            }
            if (lane == 0) g_M[b][h][row] = m - s / 7097.0f;
        }
    }
}

// ================= K3: top-34 via packed-u64 shfl reduce + write g_sel =================
__global__ void __launch_bounds__(1024) k_topk() {
    int h = blockIdx.x, b = blockIdx.y;
    int tid = threadIdx.x;
    int wid = tid >> 5, lane = tid & 31;
    __shared__ unsigned long long sk[32];

    float val = g_M[b][h][tid];
    uint32_t ub = __float_as_uint(val);
    uint32_t u = (ub & 0x80000000u) ? ~ub : (ub | 0x80000000u);
    unsigned long long key = ((unsigned long long)u << 10) | (unsigned long long)(1023 - tid);

    for (int t = 0; t < USEL; t++) {
        unsigned long long k2 = key;
#pragma unroll
        for (int off = 16; off; off >>= 1) {
            unsigned long long o = __shfl_down_sync(0xffffffffu, k2, off);
            if (o > k2) k2 = o;
        }
        if (lane == 0) sk[wid] = k2;
        __syncthreads();
        if (wid == 0) {
            unsigned long long k3 = sk[lane];
#pragma unroll
            for (int off = 16; off; off >>= 1) {
                unsigned long long o = __shfl_down_sync(0xffffffffu, k3, off);
                if (o > k3) k3 = o;
            }
            if (lane == 0) {
                sk[0] = k3;
                int widx = 1023 - (int)(k3 & 1023ull);
                g_top[b][h][t] = widx;
                g_sel[b][h][widx] = t;
            }
        }
        __syncthreads();
        int widx = 1023 - (int)(sk[0] & 1023ull);
        if (tid == widx) key = 0ull;
        __syncthreads();
    }
}

// ================= K4: PV partials with inline exp (no separate softmax) =================
__global__ void __launch_bounds__(256) k_pv(const float* __restrict__ v) {
    __shared__ float vs[CHK][64];     // 8 KB
    __shared__ float es[USEL][CHK];   // 4.25 KB
    __shared__ int   tops[USEL];
    int ch = blockIdx.x, h = blockIdx.y, b = blockIdx.z;
    int k0 = ch * CHK;
    int tid = threadIdx.x;

    if (tid < USEL) tops[tid] = g_top[b][h][tid];
    for (int u = tid; u < CHK * 64 / 4; u += 256) {
        int kk = u >> 4, c4 = (u & 15) * 4;
        *(float4*)&vs[kk][c4] = *(const float4*)&v[((size_t)b * L + k0 + kk) * D + c4];
    }
    __syncthreads();   // tops visible

    // exp weights: e = exp(S * 1/32), no max subtraction (|arg| small)
    for (int u = tid; u < USEL * CHK; u += 256) {
        int row = u >> 5, j = u & 31;
        es[row][j] = __expf(g_S[b][tops[row]][k0 + j] * 0.03125f);
    }
    __syncthreads();

    // per-chunk row sums
    if (tid < USEL) {
        float s = 0.f;
#pragma unroll
        for (int j = 0; j < CHK; j++) s += es[tid][j];
        g_psum[b][h][tid][ch] = s;
    }

    int r = tid >> 6, d = tid & 63;
    float acc[9];
#pragma unroll
    for (int i = 0; i < 9; i++) acc[i] = 0.f;

    for (int kk = 0; kk < CHK; kk += 4) {
        float v0 = vs[kk][d], v1 = vs[kk + 1][d], v2 = vs[kk + 2][d], v3 = vs[kk + 3][d];
#pragma unroll
        for (int i = 0; i < 9; i++) {
            int row = r + i * 4;
            if (row < USEL) {
                float4 e4 = *(float4*)&es[row][kk];
                acc[i] += e4.x * v0 + e4.y * v1 + e4.z * v2 + e4.w * v3;
            }
        }
    }
#pragma unroll
    for (int i = 0; i < 9; i++) {
        int row = r + i * 4;
        if (row < USEL)
            g_pacc[b][h][row][ch][d] = acc[i];
    }
}

// ================= K5: delta[b][h][i] = pacc_sum/psum_sum - meanv  (1088 blocks x 64 thr) =================
__global__ void __launch_bounds__(64) k_delta() {
    int i = blockIdx.x, h = blockIdx.y, b = blockIdx.z;
    int tid = threadIdx.x;
    __shared__ float rsv;

    if (tid < 32) {
        float s = g_psum[b][h][i][tid];
#pragma unroll
        for (int off = 16; off; off >>= 1) s += __shfl_down_sync(0xffffffffu, s, off);
        if (tid == 0) rsv = 1.0f / s;
    }
    __syncthreads();

    float s = 0.f;
#pragma unroll
    for (int c = 0; c < NCH; c++) s += g_pacc[b][h][i][c][tid];
    g_delta[b][h][i][tid] = s * rsv - g_meanv[b][tid];
}

// ================= K6: correction GEMM  E[b][h] = delta[b][h] @ W[h*64:(h+1)*64, :] =================
__global__ void __launch_bounds__(128) k_corr(const float* __restrict__ W) {
    __shared__ float sd[USEL][64];
    int nc = blockIdx.x;
    int h  = blockIdx.y, b = blockIdx.z;
    int tid = threadIdx.x;
    int n0 = nc * 128;

    for (int u = tid; u < USEL * 64 / 2; u += 128) {
        int row = u >> 5, c2 = (u & 31) * 2;
        *(float2*)&sd[row][c2] = *(const float2*)&g_delta[b][h][row][c2];
    }
    __syncthreads();

    float acc[USEL];
#pragma unroll
    for (int i = 0; i < USEL; i++) acc[i] = 0.f;

    const float* Wp = W + (size_t)(h * 64) * DMODEL + n0 + tid;
#pragma unroll 4
    for (int k = 0; k < 64; k++) {
        float w = Wp[(size_t)k * DMODEL];
#pragma unroll
        for (int i = 0; i < USEL; i++)
            acc[i] += sd[i][k] * w;
    }
#pragma unroll
    for (int i = 0; i < USEL; i++)
        g_E[b][h][i][n0 + tid] = acc[i];
}

// ================= K7: assemble out = base + sum of selected corrections =================
__global__ void __launch_bounds__(256) k_out(float* __restrict__ out) {
    __shared__ int sel[16];
    int bid = blockIdx.x;
    int b = bid >> 10, qq = bid & 1023;
    int tid = threadIdx.x;
    if (tid < 16) sel[tid] = g_sel[b][tid][qq];
    __syncthreads();

    int c4 = tid * 4;
    float4 val = *(const float4*)&g_base[b][c4];
#pragma unroll
    for (int h = 0; h < 16; h++) {
        int i = sel[h];
        if (i >= 0) {
            float4 e = *(const float4*)&g_E[b][h][i][c4];
            val.x += e.x; val.y += e.y; val.z += e.z; val.w += e.w;
        }
    }
    *(float4*)&out[(size_t)(b * L + qq) * DMODEL + c4] = val;
}

// ---------------- launch ----------------
extern "C" void kernel_launch(void* const* d_in, const int* in_sizes, int n_in,
                              void* d_out, int out_size) {
    const float* q    = (const float*)d_in[0];
    const float* k    = (const float*)d_in[1];
    const float* v    = (const float*)d_in[2];
    const float* W    = (const float*)d_in[3];
    const float* bias = (const float*)d_in[4];
    float* out = (float*)d_out;

    k_mega<<<556, 256>>>(q, k, v, bias);

    k_measure_base<<<264, 256>>>(W);

    dim3 gT(H_HEADS, BATCH);
    k_topk<<<gT, 1024>>>();

    dim3 gPV(NCH, H_HEADS, BATCH);
    k_pv<<<gPV, 256>>>(v);

    dim3 gD(USEL, H_HEADS, BATCH);
    k_delta<<<gD, 64>>>();

    dim3 gC(8, H_HEADS, BATCH);
    k_corr<<<gC, 128>>>(W);

    k_out<<<MROWS, 256>>>(out);
}

// round 10
// speedup vs baseline: 3.0392x; 1.1405x over previous
#include <cuda_runtime.h>
#include <cstdint>
#include <math.h>

// Problem constants
#define H_HEADS 16
#define BATCH   2
#define L       1024
#define D       64
#define USAMP   7097
#define USEL    34
#define DMODEL  (H_HEADS * D)   // 1024
#define MROWS   (BATCH * L)     // 2048

// PV tiling
#define NCH 32
#define CHK 32

// ---------------- scratch (static device globals; no allocation) ----------------
__device__ float g_S[BATCH][L][L];
__device__ uint8_t g_cnt8[BATCH][L][16];
__device__ float g_M[BATCH][H_HEADS][L];
__device__ int   g_top[BATCH][H_HEADS][USEL];
__device__ int   g_sel[BATCH][H_HEADS][L];     // q -> selection slot (or -1)
__device__ float g_meanv[BATCH][D];
__device__ float g_pacc[BATCH][H_HEADS][USEL][NCH][64];  // per-chunk PV partials
__device__ float g_psum[BATCH][H_HEADS][USEL][NCH];      // per-chunk exp row sums
__device__ float g_delta[BATCH][H_HEADS][USEL][D];       // s1 - meanv
__device__ float g_E[BATCH][H_HEADS][USEL][DMODEL];      // delta @ W_h
__device__ float g_base[BATCH][DMODEL];                  // bias (init), summed with partials in k_out
__device__ float g_basep[4][BATCH][DMODEL];              // K-split GEMV partials

// ---------------- threefry2x32 (JAX-compatible) ----------------
__device__ __forceinline__ uint32_t rotl32(uint32_t x, int d) {
    return (x << d) | (x >> (32 - d));
}

__device__ __forceinline__ void threefry2x32(uint32_t k0, uint32_t k1,
                                             uint32_t x0, uint32_t x1,
                                             uint32_t& o0, uint32_t& o1) {
    uint32_t ks2 = k0 ^ k1 ^ 0x1BD11BDAu;
    x0 += k0; x1 += k1;
#define TFR(r) { x0 += x1; x1 = rotl32(x1, (r)); x1 ^= x0; }
    TFR(13) TFR(15) TFR(26) TFR(6)   x0 += k1;  x1 += ks2 + 1u;
    TFR(17) TFR(29) TFR(16) TFR(24)  x0 += ks2; x1 += k0 + 2u;
    TFR(13) TFR(15) TFR(26) TFR(6)   x0 += k0;  x1 += k1 + 3u;
    TFR(17) TFR(29) TFR(16) TFR(24)  x0 += k1;  x1 += ks2 + 4u;
    TFR(13) TFR(15) TFR(26) TFR(6)   x0 += ks2; x1 += k0 + 5u;
#undef TFR
    o0 = x0; o1 = x1;
}

// ================= K1: mega prologue (scores | hist | meanv | sel-init | base-init) =================
__global__ void __launch_bounds__(256) k_mega(const float* __restrict__ q,
                                              const float* __restrict__ k,
                                              const float* __restrict__ v,
                                              const float* __restrict__ bias) {
    __shared__ union {
        struct { float qs[64][65]; float ks[64][65]; } sc;
        uint32_t hist[L];
        float part[256];
    } sm;
    int bid = blockIdx.x;
    int tid = threadIdx.x;

    if (bid < 512) {
        int b  = bid >> 8;
        int i0 = ((bid >> 4) & 15) * 64, j0 = (bid & 15) * 64;
        for (int t = tid; t < 4096; t += 256) {
            int r = t >> 6, c = t & 63;
            sm.sc.qs[r][c] = q[((size_t)b * L + i0 + r) * D + c];
            sm.sc.ks[r][c] = k[((size_t)b * L + j0 + r) * D + c];
        }
        __syncthreads();
        int tx = tid & 15, ty = tid >> 4;
        float acc[4][4] = {};
#pragma unroll 8
        for (int d = 0; d < 64; d++) {
            float a[4], bb[4];
#pragma unroll
            for (int r = 0; r < 4; r++) a[r] = sm.sc.qs[ty * 4 + r][d];
#pragma unroll
            for (int c = 0; c < 4; c++) bb[c] = sm.sc.ks[tx * 4 + c][d];
#pragma unroll
            for (int r = 0; r < 4; r++)
#pragma unroll
                for (int c = 0; c < 4; c++)
                    acc[r][c] += a[r] * bb[c];
        }
#pragma unroll
        for (int r = 0; r < 4; r++)
#pragma unroll
            for (int c = 0; c < 4; c++)
                g_S[b][i0 + ty * 4 + r][j0 + tx * 4 + c] = acc[r][c];
    } else if (bid < 544) {
        int t = bid - 512;
        int h = t & 15, b = t >> 4;
        for (int j = tid; j < L; j += 256) sm.hist[j] = 0;
        __syncthreads();
        uint32_t hk0, hk1, s0, s1;
        threefry2x32(0u, 42u, 0u, (uint32_t)h, hk0, hk1);
        threefry2x32(hk0, hk1, 0u, 1u, s0, s1);
        for (int i = tid; i < USAMP; i += 256) {
            uint32_t b1, b2;
            threefry2x32(s0, s1, 0u, (uint32_t)(b * USAMP + i), b1, b2);
            atomicAdd(&sm.hist[(b1 ^ b2) & 1023u], 1u);
        }
        __syncthreads();
        for (int j = tid; j < L; j += 256)
            g_cnt8[b][j][h] = (uint8_t)sm.hist[j];
    } else if (bid < 546) {
        int b = bid - 544;
        int d = tid & 63, g = tid >> 6;
        float s = 0.f;
        for (int kk = g; kk < L; kk += 4)
            s += v[((size_t)b * L + kk) * D + d];
        sm.part[tid] = s;
        __syncthreads();
        if (tid < 64)
            g_meanv[b][tid] = (sm.part[tid] + sm.part[tid + 64] + sm.part[tid + 128] + sm.part[tid + 192]) * (1.0f / 1024.0f);
    } else if (bid < 554) {
        int t = bid - 546;
        int base = (t * 256 + tid) * 16;
        int* sp = &g_sel[0][0][0];
#pragma unroll
        for (int e = 0; e < 16; e++) sp[base + e] = -1;
    } else {
        int b = bid - 554;
        int c4 = tid * 4;
        *(float4*)&g_base[b][c4] = *(const float4*)&bias[c4];
    }
}

// ================= K2: K-split base GEMV (blocks 0-31) + fused measure =================
__global__ void __launch_bounds__(256) k_measure_base(const float* __restrict__ W) {
    int bid = blockIdx.x;
    int tid = threadIdx.x;
    if (bid < 32) {
        // GEMV partial: b = bid>>4, kc = (bid>>2)&3, cols (bid&3)*256+tid, K in [kc*256, kc*256+256)
        int b  = bid >> 4;
        int kc = (bid >> 2) & 3;
        int c  = (bid & 3) * 256 + tid;
        __shared__ float mv[64];
        if (tid < 64) mv[tid] = g_meanv[b][tid];
        __syncthreads();
        int k0 = kc * 256;
        float a0 = 0.f, a1 = 0.f, a2 = 0.f, a3 = 0.f, a4 = 0.f, a5 = 0.f, a6 = 0.f, a7 = 0.f;
        for (int k = k0; k < k0 + 256; k += 8) {
            a0 += mv[(k)     & 63] * W[(size_t)(k)     * DMODEL + c];
            a1 += mv[(k + 1) & 63] * W[(size_t)(k + 1) * DMODEL + c];
            a2 += mv[(k + 2) & 63] * W[(size_t)(k + 2) * DMODEL + c];
            a3 += mv[(k + 3) & 63] * W[(size_t)(k + 3) * DMODEL + c];
            a4 += mv[(k + 4) & 63] * W[(size_t)(k + 4) * DMODEL + c];
            a5 += mv[(k + 5) & 63] * W[(size_t)(k + 5) * DMODEL + c];
            a6 += mv[(k + 6) & 63] * W[(size_t)(k + 6) * DMODEL + c];
            a7 += mv[(k + 7) & 63] * W[(size_t)(k + 7) * DMODEL + c];
        }
        g_basep[kc][b][c] = ((a0 + a1) + (a2 + a3)) + ((a4 + a5) + (a6 + a7));
    } else {
        // fused measure: all 16 heads in one S pass
        int mb = bid - 32;
        int wid = tid >> 5, lane = tid & 31;
        int rowg = mb * 8 + wid;
        int b = rowg >> 10, row = rowg & 1023;
        const float* Srow = g_S[b][row];
        float mx[16], sv[16];
#pragma unroll
        for (int h = 0; h < 16; h++) { mx[h] = -3.4e38f; sv[h] = 0.f; }
        for (int j = lane; j < L; j += 32) {
            float s = Srow[j];
            uint4 c16 = *(const uint4*)&g_cnt8[b][j][0];
#define HP(wrd, base) { \
            int c0 = (wrd) & 255, c1 = ((wrd) >> 8) & 255, c2 = ((wrd) >> 16) & 255, c3 = (int)((wrd) >> 24); \
            if (c0) mx[(base)]     = fmaxf(mx[(base)],     s);  sv[(base)]     += (float)c0 * s; \
            if (c1) mx[(base) + 1] = fmaxf(mx[(base) + 1], s);  sv[(base) + 1] += (float)c1 * s; \
            if (c2) mx[(base) + 2] = fmaxf(mx[(base) + 2], s);  sv[(base) + 2] += (float)c2 * s; \
            if (c3) mx[(base) + 3] = fmaxf(mx[(base) + 3], s);  sv[(base) + 3] += (float)c3 * s; }
            HP(c16.x, 0) HP(c16.y, 4) HP(c16.z, 8) HP(c16.w, 12)
#undef HP
        }
#pragma unroll
        for (int h = 0; h < 16; h++) {
            float m = mx[h], s = sv[h];
#pragma unroll
            for (int off = 16; off; off >>= 1) {
                m = fmaxf(m, __shfl_down_sync(0xffffffffu, m, off));
                s += __shfl_down_sync(0xffffffffu, s, off);
            }
            if (lane == 0) g_M[b][h][row] = m - s / 7097.0f;
        }
    }
}

// ================= K3: top-34 via radix-select on packed 42-bit keys =================
// Selection is consumed as a SET downstream; slot order is permutation-invariant.
__global__ void __launch_bounds__(1024) k_topk() {
    int h = blockIdx.x, b = blockIdx.y;
    int tid = threadIdx.x;
    __shared__ uint32_t hist[64];
    __shared__ uint32_t s_digit;
    __shared__ int s_rank;
    __shared__ int s_cnt;

    float val = g_M[b][h][tid];
    uint32_t ub = __float_as_uint(val);
    uint32_t u = (ub & 0x80000000u) ? ~ub : (ub | 0x80000000u);  // order-preserving
    unsigned long long key = ((unsigned long long)u << 10) | (unsigned long long)(1023 - tid);

    unsigned long long prefix = 0ull;
    int rank = USEL;
    if (tid == 0) s_cnt = 0;

#pragma unroll
    for (int shift = 36; shift >= 0; shift -= 6) {
        if (tid < 64) hist[tid] = 0;
        __syncthreads();
        if ((key >> (shift + 6)) == prefix)
            atomicAdd(&hist[(uint32_t)(key >> shift) & 63u], 1u);
        __syncthreads();
        if (tid == 0) {
            int c = 0;
            for (int d = 63; d >= 0; d--) {
                c += (int)hist[d];
                if (c >= rank) {
                    s_digit = (uint32_t)d;
                    s_rank = rank - (c - (int)hist[d]);
                    break;
                }
            }
        }
        __syncthreads();
        prefix = (prefix << 6) | (unsigned long long)s_digit;
        rank = s_rank;
        __syncthreads();
    }

    // prefix == 34th-largest key (keys distinct). Select key >= prefix: exactly USEL.
    if (key >= prefix) {
        int slot = atomicAdd(&s_cnt, 1);
        g_top[b][h][slot] = tid;
        g_sel[b][h][tid] = slot;
    }
}

// ================= K4: PV partials with inline exp (ILP-optimized) =================
__global__ void __launch_bounds__(256) k_pv(const float* __restrict__ v) {
    __shared__ float vs[CHK][64];     // 8 KB
    __shared__ float es[USEL][CHK];   // 4.25 KB
    __shared__ int   tops[USEL];
    int ch = blockIdx.x, h = blockIdx.y, b = blockIdx.z;
    int k0 = ch * CHK;
    int tid = threadIdx.x;

    if (tid < USEL) tops[tid] = g_top[b][h][tid];
    for (int u = tid; u < CHK * 64 / 4; u += 256) {
        int kk = u >> 4, c4 = (u & 15) * 4;
        *(float4*)&vs[kk][c4] = *(const float4*)&v[((size_t)b * L + k0 + kk) * D + c4];
    }
    __syncthreads();   // tops visible

    for (int u = tid; u < USEL * CHK; u += 256) {
        int row = u >> 5, j = u & 31;
        es[row][j] = __expf(g_S[b][tops[row]][k0 + j] * 0.03125f);
    }
    __syncthreads();

    if (tid < USEL) {
        float s = 0.f;
#pragma unroll
        for (int j = 0; j < CHK; j++) s += es[tid][j];
        g_psum[b][h][tid][ch] = s;
    }

    int r = tid >> 6, d = tid & 63;
    float acc[9];
#pragma unroll
    for (int i = 0; i < 9; i++) acc[i] = 0.f;
    bool has9 = (r < 2);

#pragma unroll
    for (int kk = 0; kk < CHK; kk += 4) {
        float v0 = vs[kk][d], v1 = vs[kk + 1][d], v2 = vs[kk + 2][d], v3 = vs[kk + 3][d];
        float4 e[9];
#pragma unroll
        for (int i = 0; i < 8; i++)
            e[i] = *(float4*)&es[r + i * 4][kk];
        if (has9) e[8] = *(float4*)&es[r + 32][kk];
#pragma unroll
        for (int i = 0; i < 8; i++)
            acc[i] += e[i].x * v0 + e[i].y * v1 + e[i].z * v2 + e[i].w * v3;
        if (has9)
            acc[8] += e[8].x * v0 + e[8].y * v1 + e[8].z * v2 + e[8].w * v3;
    }
#pragma unroll
    for (int i = 0; i < 8; i++)
        g_pacc[b][h][r + i * 4][ch][d] = acc[i];
    if (has9)
        g_pacc[b][h][r + 32][ch][d] = acc[8];
}

// ================= K5: delta = pacc_sum/psum_sum - meanv =================
__global__ void __launch_bounds__(64) k_delta() {
    int i = blockIdx.x, h = blockIdx.y, b = blockIdx.z;
    int tid = threadIdx.x;
    __shared__ float rsv;

    if (tid < 32) {
        float s = g_psum[b][h][i][tid];
#pragma unroll
        for (int off = 16; off; off >>= 1) s += __shfl_down_sync(0xffffffffu, s, off);
        if (tid == 0) rsv = 1.0f / s;
    }
    __syncthreads();

    float s = 0.f;
#pragma unroll
    for (int c = 0; c < NCH; c++) s += g_pacc[b][h][i][c][tid];
    g_delta[b][h][i][tid] = s * rsv - g_meanv[b][tid];
}

// ================= K6: correction GEMM  E[b][h] = delta[b][h] @ W[h*64:(h+1)*64, :] =================
__global__ void __launch_bounds__(128) k_corr(const float* __restrict__ W) {
    __shared__ float sd[USEL][64];
    int nc = blockIdx.x;
    int h  = blockIdx.y, b = blockIdx.z;
    int tid = threadIdx.x;
    int n0 = nc * 128;

    for (int u = tid; u < USEL * 64 / 2; u += 128) {
        int row = u >> 5, c2 = (u & 31) * 2;
        *(float2*)&sd[row][c2] = *(const float2*)&g_delta[b][h][row][c2];
    }
    __syncthreads();

    float acc[USEL];
#pragma unroll
    for (int i = 0; i < USEL; i++) acc[i] = 0.f;

    const float* Wp = W + (size_t)(h * 64) * DMODEL + n0 + tid;
#pragma unroll 4
    for (int k = 0; k < 64; k++) {
        float w = Wp[(size_t)k * DMODEL];
#pragma unroll
        for (int i = 0; i < USEL; i++)
            acc[i] += sd[i][k] * w;
    }
#pragma unroll
    for (int i = 0; i < USEL; i++)
        g_E[b][h][i][n0 + tid] = acc[i];
}

// ================= K7: assemble out = bias + GEMV partials + selected corrections =================
__global__ void __launch_bounds__(256) k_out(float* __restrict__ out) {
    __shared__ int sel[16];
    int bid = blockIdx.x;
    int b = bid >> 10, qq = bid & 1023;
    int tid = threadIdx.x;
    if (tid < 16) sel[tid] = g_sel[b][tid][qq];
    __syncthreads();

    int c4 = tid * 4;
    float4 val = *(const float4*)&g_base[b][c4];
#pragma unroll
    for (int kc = 0; kc < 4; kc++) {
        float4 p = *(const float4*)&g_basep[kc][b][c4];
        val.x += p.x; val.y += p.y; val.z += p.z; val.w += p.w;
    }
#pragma unroll
    for (int h = 0; h < 16; h++) {
        int i = sel[h];
        if (i >= 0) {
            float4 e = *(const float4*)&g_E[b][h][i][c4];
            val.x += e.x; val.y += e.y; val.z += e.z; val.w += e.w;
        }
    }
    *(float4*)&out[(size_t)(b * L + qq) * DMODEL + c4] = val;
}

// ---------------- launch ----------------
extern "C" void kernel_launch(void* const* d_in, const int* in_sizes, int n_in,
                              void* d_out, int out_size) {
    const float* q    = (const float*)d_in[0];
    const float* k    = (const float*)d_in[1];
    const float* v    = (const float*)d_in[2];
    const float* W    = (const float*)d_in[3];
    const float* bias = (const float*)d_in[4];
    float* out = (float*)d_out;

    k_mega<<<556, 256>>>(q, k, v, bias);

    k_measure_base<<<288, 256>>>(W);

    dim3 gT(H_HEADS, BATCH);
    k_topk<<<gT, 1024>>>();

    dim3 gPV(NCH, H_HEADS, BATCH);
    k_pv<<<gPV, 256>>>(v);

    dim3 gD(USEL, H_HEADS, BATCH);
    k_delta<<<gD, 64>>>();

    dim3 gC(8, H_HEADS, BATCH);
    k_corr<<<gC, 128>>>(W);

    k_out<<<MROWS, 256>>>(out);
}

// round 11
// speedup vs baseline: 3.1942x; 1.0510x over previous
#include <cuda_runtime.h>
#include <cstdint>
#include <math.h>

// Problem constants
#define H_HEADS 16
#define BATCH   2
#define L       1024
#define D       64
#define USAMP   7097
#define USEL    34
#define DMODEL  (H_HEADS * D)   // 1024
#define MROWS   (BATCH * L)     // 2048

// PV tiling
#define NCH 64
#define CHK 16

// ---------------- scratch (static device globals; no allocation) ----------------
__device__ float g_S[BATCH][L][L];
__device__ uint8_t g_cnt8[BATCH][L][16];
__device__ float g_M[BATCH][H_HEADS][L];
__device__ int   g_top[BATCH][H_HEADS][USEL];
__device__ int   g_sel[BATCH][H_HEADS][L];     // q -> selection slot (or -1)
__device__ float g_meanv[BATCH][D];
__device__ float g_pacc[BATCH][H_HEADS][USEL][NCH][64];  // per-chunk PV partials
__device__ float g_psum[BATCH][H_HEADS][USEL][NCH];      // per-chunk exp row sums
__device__ float g_delta[BATCH][H_HEADS][USEL][D];       // s1 - meanv
__device__ float g_E[BATCH][H_HEADS][USEL][DMODEL];      // delta @ W_h
__device__ float g_base[BATCH][DMODEL];                  // bias (init)
__device__ float g_basep[4][BATCH][DMODEL];              // K-split GEMV partials

// ---------------- threefry2x32 (JAX-compatible) ----------------
__device__ __forceinline__ uint32_t rotl32(uint32_t x, int d) {
    return (x << d) | (x >> (32 - d));
}

__device__ __forceinline__ void threefry2x32(uint32_t k0, uint32_t k1,
                                             uint32_t x0, uint32_t x1,
                                             uint32_t& o0, uint32_t& o1) {
    uint32_t ks2 = k0 ^ k1 ^ 0x1BD11BDAu;
    x0 += k0; x1 += k1;
#define TFR(r) { x0 += x1; x1 = rotl32(x1, (r)); x1 ^= x0; }
    TFR(13) TFR(15) TFR(26) TFR(6)   x0 += k1;  x1 += ks2 + 1u;
    TFR(17) TFR(29) TFR(16) TFR(24)  x0 += ks2; x1 += k0 + 2u;
    TFR(13) TFR(15) TFR(26) TFR(6)   x0 += k0;  x1 += k1 + 3u;
    TFR(17) TFR(29) TFR(16) TFR(24)  x0 += k1;  x1 += ks2 + 4u;
    TFR(13) TFR(15) TFR(26) TFR(6)   x0 += ks2; x1 += k0 + 5u;
#undef TFR
    o0 = x0; o1 = x1;
}

// ================= K1: mega prologue (scores | hist | meanv | sel-init | base-init) =================
__global__ void __launch_bounds__(256) k_mega(const float* __restrict__ q,
                                              const float* __restrict__ k,
                                              const float* __restrict__ v,
                                              const float* __restrict__ bias) {
    __shared__ union {
        struct { float qt[64][68]; float kt[64][68]; } sc;   // transposed [d][row], 16B-aligned stride
        uint32_t hist[L];
        float part[256];
    } sm;
    int bid = blockIdx.x;
    int tid = threadIdx.x;

    if (bid < 512) {
        // ---- scores: S[b] = q[b] @ k[b]^T ; smem transposed for float4 fragment loads ----
        int b  = bid >> 8;
        int i0 = ((bid >> 4) & 15) * 64, j0 = (bid & 15) * 64;
        for (int t = tid; t < 4096; t += 256) {
            int r = t >> 6, c = t & 63;
            sm.sc.qt[c][r] = q[((size_t)b * L + i0 + r) * D + c];
            sm.sc.kt[c][r] = k[((size_t)b * L + j0 + r) * D + c];
        }
        __syncthreads();
        int tx = tid & 15, ty = tid >> 4;
        float acc[4][4] = {};
#pragma unroll 8
        for (int d = 0; d < 64; d++) {
            float4 a4 = *(const float4*)&sm.sc.qt[d][ty * 4];
            float4 b4 = *(const float4*)&sm.sc.kt[d][tx * 4];
            float a[4] = {a4.x, a4.y, a4.z, a4.w};
            float bb[4] = {b4.x, b4.y, b4.z, b4.w};
#pragma unroll
            for (int r = 0; r < 4; r++)
#pragma unroll
                for (int c = 0; c < 4; c++)
                    acc[r][c] += a[r] * bb[c];
        }
#pragma unroll
        for (int r = 0; r < 4; r++)
#pragma unroll
            for (int c = 0; c < 4; c++)
                g_S[b][i0 + ty * 4 + r][j0 + tx * 4 + c] = acc[r][c];
    } else if (bid < 544) {
        int t = bid - 512;
        int h = t & 15, b = t >> 4;
        for (int j = tid; j < L; j += 256) sm.hist[j] = 0;
        __syncthreads();
        uint32_t hk0, hk1, s0, s1;
        threefry2x32(0u, 42u, 0u, (uint32_t)h, hk0, hk1);
        threefry2x32(hk0, hk1, 0u, 1u, s0, s1);
        for (int i = tid; i < USAMP; i += 256) {
            uint32_t b1, b2;
            threefry2x32(s0, s1, 0u, (uint32_t)(b * USAMP + i), b1, b2);
            atomicAdd(&sm.hist[(b1 ^ b2) & 1023u], 1u);
        }
        __syncthreads();
        for (int j = tid; j < L; j += 256)
            g_cnt8[b][j][h] = (uint8_t)sm.hist[j];
    } else if (bid < 546) {
        int b = bid - 544;
        int d = tid & 63, g = tid >> 6;
        float s = 0.f;
        for (int kk = g; kk < L; kk += 4)
            s += v[((size_t)b * L + kk) * D + d];
        sm.part[tid] = s;
        __syncthreads();
        if (tid < 64)
            g_meanv[b][tid] = (sm.part[tid] + sm.part[tid + 64] + sm.part[tid + 128] + sm.part[tid + 192]) * (1.0f / 1024.0f);
    } else if (bid < 554) {
        int t = bid - 546;
        int base = (t * 256 + tid) * 16;
        int* sp = &g_sel[0][0][0];
#pragma unroll
        for (int e = 0; e < 16; e++) sp[base + e] = -1;
    } else {
        int b = bid - 554;
        int c4 = tid * 4;
        *(float4*)&g_base[b][c4] = *(const float4*)&bias[c4];
    }
}

// ================= K2: K-split base GEMV (blocks 0-31) + fused measure =================
__global__ void __launch_bounds__(256) k_measure_base(const float* __restrict__ W) {
    int bid = blockIdx.x;
    int tid = threadIdx.x;
    if (bid < 32) {
        int b  = bid >> 4;
        int kc = (bid >> 2) & 3;
        int c  = (bid & 3) * 256 + tid;
        __shared__ float mv[64];
        if (tid < 64) mv[tid] = g_meanv[b][tid];
        __syncthreads();
        int k0 = kc * 256;
        float a0 = 0.f, a1 = 0.f, a2 = 0.f, a3 = 0.f, a4 = 0.f, a5 = 0.f, a6 = 0.f, a7 = 0.f;
        for (int k = k0; k < k0 + 256; k += 8) {
            a0 += mv[(k)     & 63] * W[(size_t)(k)     * DMODEL + c];
            a1 += mv[(k + 1) & 63] * W[(size_t)(k + 1) * DMODEL + c];
            a2 += mv[(k + 2) & 63] * W[(size_t)(k + 2) * DMODEL + c];
            a3 += mv[(k + 3) & 63] * W[(size_t)(k + 3) * DMODEL + c];
            a4 += mv[(k + 4) & 63] * W[(size_t)(k + 4) * DMODEL + c];
            a5 += mv[(k + 5) & 63] * W[(size_t)(k + 5) * DMODEL + c];
            a6 += mv[(k + 6) & 63] * W[(size_t)(k + 6) * DMODEL + c];
            a7 += mv[(k + 7) & 63] * W[(size_t)(k + 7) * DMODEL + c];
        }
        g_basep[kc][b][c] = ((a0 + a1) + (a2 + a3)) + ((a4 + a5) + (a6 + a7));
    } else {
        int mb = bid - 32;
        int wid = tid >> 5, lane = tid & 31;
        int rowg = mb * 8 + wid;
        int b = rowg >> 10, row = rowg & 1023;
        const float* Srow = g_S[b][row];
        float mx[16], sv[16];
#pragma unroll
        for (int h = 0; h < 16; h++) { mx[h] = -3.4e38f; sv[h] = 0.f; }
        for (int j = lane; j < L; j += 32) {
            float s = Srow[j];
            uint4 c16 = *(const uint4*)&g_cnt8[b][j][0];
#define HP(wrd, base) { \
            int c0 = (wrd) & 255, c1 = ((wrd) >> 8) & 255, c2 = ((wrd) >> 16) & 255, c3 = (int)((wrd) >> 24); \
            if (c0) mx[(base)]     = fmaxf(mx[(base)],     s);  sv[(base)]     += (float)c0 * s; \
            if (c1) mx[(base) + 1] = fmaxf(mx[(base) + 1], s);  sv[(base) + 1] += (float)c1 * s; \
            if (c2) mx[(base) + 2] = fmaxf(mx[(base) + 2], s);  sv[(base) + 2] += (float)c2 * s; \
            if (c3) mx[(base) + 3] = fmaxf(mx[(base) + 3], s);  sv[(base) + 3] += (float)c3 * s; }
            HP(c16.x, 0) HP(c16.y, 4) HP(c16.z, 8) HP(c16.w, 12)
#undef HP
        }
#pragma unroll
        for (int h = 0; h < 16; h++) {
            float m = mx[h], s = sv[h];
#pragma unroll
            for (int off = 16; off; off >>= 1) {
                m = fmaxf(m, __shfl_down_sync(0xffffffffu, m, off));
                s += __shfl_down_sync(0xffffffffu, s, off);
            }
            if (lane == 0) g_M[b][h][row] = m - s / 7097.0f;
        }
    }
}

// ================= K3: top-34 via radix-select on packed 42-bit keys =================
__global__ void __launch_bounds__(1024) k_topk() {
    int h = blockIdx.x, b = blockIdx.y;
    int tid = threadIdx.x;
    __shared__ uint32_t hist[64];
    __shared__ uint32_t s_digit;
    __shared__ int s_rank;
    __shared__ int s_cnt;

    float val = g_M[b][h][tid];
    uint32_t ub = __float_as_uint(val);
    uint32_t u = (ub & 0x80000000u) ? ~ub : (ub | 0x80000000u);
    unsigned long long key = ((unsigned long long)u << 10) | (unsigned long long)(1023 - tid);

    unsigned long long prefix = 0ull;
    int rank = USEL;
    if (tid == 0) s_cnt = 0;

#pragma unroll
    for (int shift = 36; shift >= 0; shift -= 6) {
        if (tid < 64) hist[tid] = 0;
        __syncthreads();
        if ((key >> (shift + 6)) == prefix)
            atomicAdd(&hist[(uint32_t)(key >> shift) & 63u], 1u);
        __syncthreads();
        if (tid == 0) {
            int c = 0;
            for (int d = 63; d >= 0; d--) {
                c += (int)hist[d];
                if (c >= rank) {
                    s_digit = (uint32_t)d;
                    s_rank = rank - (c - (int)hist[d]);
                    break;
                }
            }
        }
        __syncthreads();
        prefix = (prefix << 6) | (unsigned long long)s_digit;
        rank = s_rank;
        __syncthreads();
    }

    if (key >= prefix) {
        int slot = atomicAdd(&s_cnt, 1);
        g_top[b][h][slot] = tid;
        g_sel[b][h][tid] = slot;
    }
}

// ================= K4: PV partials with inline exp (CHK=16, 2048 blocks) =================
__global__ void __launch_bounds__(256) k_pv(const float* __restrict__ v) {
    __shared__ float vs[CHK][64];     // 4 KB
    __shared__ float es[USEL][CHK];   // 2.2 KB
    __shared__ int   tops[USEL];
    int ch = blockIdx.x, h = blockIdx.y, b = blockIdx.z;
    int k0 = ch * CHK;
    int tid = threadIdx.x;

    if (tid < USEL) tops[tid] = g_top[b][h][tid];
    {
        int u = tid;   // 256 = CHK*64/4 exactly
        int kk = u >> 4, c4 = (u & 15) * 4;
        *(float4*)&vs[kk][c4] = *(const float4*)&v[((size_t)b * L + k0 + kk) * D + c4];
    }
    __syncthreads();   // tops visible

    for (int u = tid; u < USEL * CHK; u += 256) {
        int row = u >> 4, j = u & 15;
        es[row][j] = __expf(g_S[b][tops[row]][k0 + j] * 0.03125f);
    }
    __syncthreads();

    if (tid < USEL) {
        float s = 0.f;
#pragma unroll
        for (int j = 0; j < CHK; j++) s += es[tid][j];
        g_psum[b][h][tid][ch] = s;
    }

    int r = tid >> 6, d = tid & 63;
    float acc[9];
#pragma unroll
    for (int i = 0; i < 9; i++) acc[i] = 0.f;
    bool has9 = (r < 2);

#pragma unroll
    for (int kk = 0; kk < CHK; kk += 4) {
        float v0 = vs[kk][d], v1 = vs[kk + 1][d], v2 = vs[kk + 2][d], v3 = vs[kk + 3][d];
        float4 e[9];
#pragma unroll
        for (int i = 0; i < 8; i++)
            e[i] = *(float4*)&es[r + i * 4][kk];
        if (has9) e[8] = *(float4*)&es[r + 32][kk];
#pragma unroll
        for (int i = 0; i < 8; i++)
            acc[i] += e[i].x * v0 + e[i].y * v1 + e[i].z * v2 + e[i].w * v3;
        if (has9)
            acc[8] += e[8].x * v0 + e[8].y * v1 + e[8].z * v2 + e[8].w * v3;
    }
#pragma unroll
    for (int i = 0; i < 8; i++)
        g_pacc[b][h][r + i * 4][ch][d] = acc[i];
    if (has9)
        g_pacc[b][h][r + 32][ch][d] = acc[8];
}

// ================= K5: delta = pacc_sum/psum_sum - meanv =================
__global__ void __launch_bounds__(64) k_delta() {
    int i = blockIdx.x, h = blockIdx.y, b = blockIdx.z;
    int tid = threadIdx.x;
    __shared__ float rsv;

    if (tid < 32) {
        float s = g_psum[b][h][i][tid] + g_psum[b][h][i][tid + 32];
#pragma unroll
        for (int off = 16; off; off >>= 1) s += __shfl_down_sync(0xffffffffu, s, off);
        if (tid == 0) rsv = 1.0f / s;
    }
    __syncthreads();

    float s = 0.f;
#pragma unroll
    for (int c = 0; c < NCH; c++) s += g_pacc[b][h][i][c][tid];
    g_delta[b][h][i][tid] = s * rsv - g_meanv[b][tid];
}

// ================= K6: correction GEMM  E[b][h] = delta[b][h] @ W[h*64:(h+1)*64, :] =================
__global__ void __launch_bounds__(128) k_corr(const float* __restrict__ W) {
    __shared__ float sd[USEL][64];
    int nc = blockIdx.x;
    int h  = blockIdx.y, b = blockIdx.z;
    int tid = threadIdx.x;
    int n0 = nc * 128;

    for (int u = tid; u < USEL * 64 / 2; u += 128) {
        int row = u >> 5, c2 = (u & 31) * 2;
        *(float2*)&sd[row][c2] = *(const float2*)&g_delta[b][h][row][c2];
    }
    __syncthreads();

    float acc[USEL];
#pragma unroll
    for (int i = 0; i < USEL; i++) acc[i] = 0.f;

    const float* Wp = W + (size_t)(h * 64) * DMODEL + n0 + tid;
#pragma unroll 4
    for (int k = 0; k < 64; k++) {
        float w = Wp[(size_t)k * DMODEL];
#pragma unroll
        for (int i = 0; i < USEL; i++)
            acc[i] += sd[i][k] * w;
    }
#pragma unroll
    for (int i = 0; i < USEL; i++)
        g_E[b][h][i][n0 + tid] = acc[i];
}

// ================= K7: assemble out = bias + GEMV partials + selected corrections =================
__global__ void __launch_bounds__(256) k_out(float* __restrict__ out) {
    __shared__ int sel[16];
    int bid = blockIdx.x;
    int b = bid >> 10, qq = bid & 1023;
    int tid = threadIdx.x;
    if (tid < 16) sel[tid] = g_sel[b][tid][qq];
    __syncthreads();

    int c4 = tid * 4;
    float4 val = *(const float4*)&g_base[b][c4];
#pragma unroll
    for (int kc = 0; kc < 4; kc++) {
        float4 p = *(const float4*)&g_basep[kc][b][c4];
        val.x += p.x; val.y += p.y; val.z += p.z; val.w += p.w;
    }
#pragma unroll
    for (int h = 0; h < 16; h++) {
        int i = sel[h];
        if (i >= 0) {
            float4 e = *(const float4*)&g_E[b][h][i][c4];
            val.x += e.x; val.y += e.y; val.z += e.z; val.w += e.w;
        }
    }
    *(float4*)&out[(size_t)(b * L + qq) * DMODEL + c4] = val;
}

// ---------------- launch ----------------
extern "C" void kernel_launch(void* const* d_in, const int* in_sizes, int n_in,
                              void* d_out, int out_size) {
    const float* q    = (const float*)d_in[0];
    const float* k    = (const float*)d_in[1];
    const float* v    = (const float*)d_in[2];
    const float* W    = (const float*)d_in[3];
    const float* bias = (const float*)d_in[4];
    float* out = (float*)d_out;

    k_mega<<<556, 256>>>(q, k, v, bias);

    k_measure_base<<<288, 256>>>(W);

    dim3 gT(H_HEADS, BATCH);
    k_topk<<<gT, 1024>>>();

    dim3 gPV(NCH, H_HEADS, BATCH);
    k_pv<<<gPV, 256>>>(v);

    dim3 gD(USEL, H_HEADS, BATCH);
    k_delta<<<gD, 64>>>();

    dim3 gC(8, H_HEADS, BATCH);
    k_corr<<<gC, 128>>>(W);

    k_out<<<MROWS, 256>>>(out);
}